// round 1
// baseline (speedup 1.0000x reference)
#include <cuda_runtime.h>
#include <cuda_bf16.h>

#define B_   8
#define S_   2048
#define E_   256
#define H_   4
#define D_   64
#define M_TOT (B_*S_)
#define QT   8          // queries per attention block
#define KT_ROWS (QT + 2*64)   // 136 key rows per tile

// -------- scratch (static device memory; no allocation allowed) --------
__device__ float g_qkv[3ull * B_ * H_ * S_ * D_];   // [sec][b][h][s][d]
__device__ float g_attn[(size_t)M_TOT * E_];        // [m][e]
__device__ float g_proj[(size_t)M_TOT * E_];        // [m][e]
__device__ float g_ctx[B_ * E_];

// ======================================================================
// Kernel 1: fused embed-gather + QKV GEMM.  C[m,n] = emb[text[m]] @ W^T + b
// M=16384, N=768, K=256.  BM=BN=64, BK=32, 256 thr, 4x4 per thread.
// Epilogue scatters into q/k/v [b,h,s,d] layout, q scaled by 1/8.
// ======================================================================
__global__ void __launch_bounds__(256) qkv_gemm(const int* __restrict__ text,
                                                const float* __restrict__ emb,
                                                const float* __restrict__ W,
                                                const float* __restrict__ bias) {
    __shared__ float As[32][64];
    __shared__ float Ws[32][68];
    __shared__ int   tok_s[64];

    const int tid = threadIdx.x;
    const int tx = tid & 15, ty = tid >> 4;
    const int m0 = blockIdx.x * 64, n0 = blockIdx.y * 64;

    if (tid < 64) tok_s[tid] = text[m0 + tid];

    float acc[4][4] = {};

    for (int kt = 0; kt < 256; kt += 32) {
        __syncthreads();
        #pragma unroll
        for (int it = 0; it < 2; ++it) {
            int idx = tid + it * 256;
            int row = idx >> 3;
            int c4  = (idx & 7) * 4;
            const float* arow = emb + (size_t)tok_s[row] * 256;
            float4 av = *(const float4*)&arow[kt + c4];
            As[c4+0][row] = av.x; As[c4+1][row] = av.y;
            As[c4+2][row] = av.z; As[c4+3][row] = av.w;
            float4 wv = *(const float4*)&W[(size_t)(n0 + row) * 256 + kt + c4];
            Ws[c4+0][row] = wv.x; Ws[c4+1][row] = wv.y;
            Ws[c4+2][row] = wv.z; Ws[c4+3][row] = wv.w;
        }
        __syncthreads();
        #pragma unroll
        for (int k = 0; k < 32; ++k) {
            float4 a = *(const float4*)&As[k][ty * 4];
            float4 w = *(const float4*)&Ws[k][tx * 4];
            float av[4] = {a.x, a.y, a.z, a.w};
            float wv[4] = {w.x, w.y, w.z, w.w};
            #pragma unroll
            for (int i = 0; i < 4; ++i)
                #pragma unroll
                for (int j = 0; j < 4; ++j)
                    acc[i][j] += av[i] * wv[j];
        }
    }

    const int sec = n0 >> 8;
    const int h   = (n0 >> 6) & 3;
    const float scale = (sec == 0) ? 0.125f : 1.0f;
    float4 bb = *(const float4*)&bias[n0 + tx * 4];

    #pragma unroll
    for (int i = 0; i < 4; ++i) {
        int m = m0 + ty * 4 + i;
        int b = m >> 11, s = m & 2047;
        float4 o;
        o.x = (acc[i][0] + bb.x) * scale;
        o.y = (acc[i][1] + bb.y) * scale;
        o.z = (acc[i][2] + bb.z) * scale;
        o.w = (acc[i][3] + bb.w) * scale;
        float* ptr = g_qkv + ((((size_t)sec * B_ + b) * H_ + h) * S_ + s) * 64 + tx * 4;
        *(float4*)ptr = o;
    }
}

// ======================================================================
// Kernel 2: banded attention.  1 block = (b,h, 8 queries) = 8 warps.
// K/V window rows staged in SMEM; per-lane key-parallel dots.
// ======================================================================
__global__ void __launch_bounds__(256) attn_kernel() {
    extern __shared__ float smem[];
    float* K_s = smem;                       // [136][65]
    float* V_s = K_s + KT_ROWS * 65;         // [136][64]
    float* q_s = V_s + KT_ROWS * 64;         // [8][64]
    float* p_s = q_s + QT * 64;              // [8][132]

    const int nq = S_ / QT;
    const int qt = blockIdx.x % nq;
    const int h  = (blockIdx.x / nq) % H_;
    const int b  = blockIdx.x / (nq * H_);

    const int q0 = qt * QT;
    const int kstart = q0 - 64;

    const float* qb = g_qkv + ((size_t)(b * H_ + h)) * S_ * 64;
    const float* kb = g_qkv + ((size_t)(B_ * H_) + b * H_ + h) * S_ * 64;
    const float* vb = g_qkv + ((size_t)(2 * B_ * H_) + b * H_ + h) * S_ * 64;

    const int tid = threadIdx.x;
    // load K/V window (zero-fill out of range)
    for (int idx = tid; idx < KT_ROWS * 64; idx += 256) {
        int row = idx >> 6, d = idx & 63;
        int kg = kstart + row;
        bool in = (kg >= 0) && (kg < S_);
        K_s[row * 65 + d] = in ? kb[(size_t)kg * 64 + d] : 0.f;
        V_s[row * 64 + d] = in ? vb[(size_t)kg * 64 + d] : 0.f;
    }
    for (int idx = tid; idx < QT * 64; idx += 256) {
        int r = idx >> 6, d = idx & 63;
        q_s[r * 64 + d] = qb[(size_t)(q0 + r) * 64 + d];
    }
    __syncthreads();

    const int w = tid >> 5;      // warp = query
    const int lane = tid & 31;
    const int s = q0 + w;

    float sc[5];
    #pragma unroll
    for (int r = 0; r < 5; ++r) {
        int t = lane + 32 * r;
        float a = -3.0e38f;
        if (t <= 128) {
            int j = w + t;
            int kg = kstart + j;
            if (kg >= 0 && kg < S_) {
                float acc = 0.f;
                const float* qr = q_s + w * 64;
                const float* kr = K_s + j * 65;
                #pragma unroll 8
                for (int d = 0; d < 64; ++d) acc += qr[d] * kr[d];
                a = acc;
            }
        }
        sc[r] = a;
    }
    // softmax over the 129 scores
    float mx = sc[0];
    #pragma unroll
    for (int r = 1; r < 5; ++r) mx = fmaxf(mx, sc[r]);
    #pragma unroll
    for (int off = 16; off > 0; off >>= 1)
        mx = fmaxf(mx, __shfl_xor_sync(0xffffffffu, mx, off));
    float sum = 0.f;
    #pragma unroll
    for (int r = 0; r < 5; ++r) {
        float p = __expf(sc[r] - mx);   // masked -> exp(-huge) = 0
        sc[r] = p;
        sum += p;
    }
    #pragma unroll
    for (int off = 16; off > 0; off >>= 1)
        sum += __shfl_xor_sync(0xffffffffu, sum, off);
    float inv = 1.0f / sum;
    #pragma unroll
    for (int r = 0; r < 5; ++r) {
        int t = lane + 32 * r;
        if (t <= 128) p_s[w * 132 + t] = sc[r] * inv;
    }
    __syncwarp();

    // output: lane owns 2 dims
    const int d0 = lane * 2;
    float a0 = 0.f, a1 = 0.f;
    #pragma unroll 4
    for (int t = 0; t <= 128; ++t) {
        float p = p_s[w * 132 + t];
        float2 v = *(const float2*)&V_s[(w + t) * 64 + d0];
        a0 += p * v.x;
        a1 += p * v.y;
    }
    float2 o = {a0, a1};
    *(float2*)&g_attn[((size_t)(b * S_ + s)) * 256 + h * 64 + d0] = o;
}

// ======================================================================
// Kernel 3: output projection GEMM.  M=16384, N=256, K=256.
// ======================================================================
__global__ void __launch_bounds__(256) proj_gemm(const float* __restrict__ W,
                                                 const float* __restrict__ bias) {
    __shared__ float As[32][64];
    __shared__ float Ws[32][68];

    const int tid = threadIdx.x;
    const int tx = tid & 15, ty = tid >> 4;
    const int m0 = blockIdx.x * 64, n0 = blockIdx.y * 64;

    float acc[4][4] = {};

    for (int kt = 0; kt < 256; kt += 32) {
        __syncthreads();
        #pragma unroll
        for (int it = 0; it < 2; ++it) {
            int idx = tid + it * 256;
            int row = idx >> 3;
            int c4  = (idx & 7) * 4;
            float4 av = *(const float4*)&g_attn[(size_t)(m0 + row) * 256 + kt + c4];
            As[c4+0][row] = av.x; As[c4+1][row] = av.y;
            As[c4+2][row] = av.z; As[c4+3][row] = av.w;
            float4 wv = *(const float4*)&W[(size_t)(n0 + row) * 256 + kt + c4];
            Ws[c4+0][row] = wv.x; Ws[c4+1][row] = wv.y;
            Ws[c4+2][row] = wv.z; Ws[c4+3][row] = wv.w;
        }
        __syncthreads();
        #pragma unroll
        for (int k = 0; k < 32; ++k) {
            float4 a = *(const float4*)&As[k][ty * 4];
            float4 w = *(const float4*)&Ws[k][tx * 4];
            float av[4] = {a.x, a.y, a.z, a.w};
            float wv[4] = {w.x, w.y, w.z, w.w};
            #pragma unroll
            for (int i = 0; i < 4; ++i)
                #pragma unroll
                for (int j = 0; j < 4; ++j)
                    acc[i][j] += av[i] * wv[j];
        }
    }

    float4 bb = *(const float4*)&bias[n0 + tx * 4];
    #pragma unroll
    for (int i = 0; i < 4; ++i) {
        int m = m0 + ty * 4 + i;
        float4 o;
        o.x = acc[i][0] + bb.x;
        o.y = acc[i][1] + bb.y;
        o.z = acc[i][2] + bb.z;
        o.w = acc[i][3] + bb.w;
        *(float4*)&g_proj[(size_t)m * 256 + n0 + tx * 4] = o;
    }
}

// ======================================================================
// Kernel 4: max-pool over sequence.  block = batch, thread = channel.
// ======================================================================
__global__ void __launch_bounds__(256) pool_kernel() {
    int b = blockIdx.x, e = threadIdx.x;
    float mx = -3.0e38f;
    const float* base = g_proj + (size_t)b * S_ * 256 + e;
    #pragma unroll 8
    for (int s = 0; s < S_; ++s) mx = fmaxf(mx, base[(size_t)s * 256]);
    g_ctx[b * 256 + e] = mx;
}

// ======================================================================
// Kernel 5: MLP head (tiny).  One block, layers in SMEM.
// ======================================================================
__global__ void __launch_bounds__(256) mlp_kernel(const float* __restrict__ fc1w,
                                                  const float* __restrict__ fc1b,
                                                  const float* __restrict__ fc2w,
                                                  const float* __restrict__ fc2b,
                                                  const float* __restrict__ fc3w,
                                                  const float* __restrict__ fc3b,
                                                  float* __restrict__ out) {
    __shared__ float ctx_s[8 * 256];
    __shared__ float h1_s[8 * 512];
    __shared__ float h2_s[8 * 256];
    const int tid = threadIdx.x;

    for (int i = tid; i < 8 * 256; i += 256) ctx_s[i] = g_ctx[i];
    __syncthreads();

    for (int i = tid; i < 8 * 512; i += 256) {
        int b = i >> 9, o = i & 511;
        float acc = fc1b[o];
        const float* w = fc1w + (size_t)o * 256;
        const float* x = ctx_s + b * 256;
        #pragma unroll 8
        for (int k = 0; k < 256; ++k) acc += x[k] * w[k];
        h1_s[i] = acc > 0.f ? acc : 0.01f * acc;
    }
    __syncthreads();

    for (int i = tid; i < 8 * 256; i += 256) {
        int b = i >> 8, o = i & 255;
        float acc = fc2b[o];
        const float* w = fc2w + (size_t)o * 512;
        const float* x = h1_s + b * 512;
        #pragma unroll 8
        for (int k = 0; k < 512; ++k) acc += x[k] * w[k];
        h2_s[i] = acc > 0.f ? acc : 0.01f * acc;
    }
    __syncthreads();

    if (tid < 8 * 20) {
        int b = tid / 20, o = tid % 20;
        float acc = fc3b[o];
        const float* w = fc3w + (size_t)o * 256;
        const float* x = h2_s + b * 256;
        #pragma unroll 8
        for (int k = 0; k < 256; ++k) acc += x[k] * w[k];
        out[b * 20 + o] = acc;
    }
}

// ======================================================================
extern "C" void kernel_launch(void* const* d_in, const int* in_sizes, int n_in,
                              void* d_out, int out_size) {
    const int*   text   = (const int*)d_in[0];
    const float* emb    = (const float*)d_in[1];
    const float* ipw    = (const float*)d_in[2];
    const float* ipb    = (const float*)d_in[3];
    const float* opw    = (const float*)d_in[4];
    const float* opb    = (const float*)d_in[5];
    const float* fc1w   = (const float*)d_in[6];
    const float* fc1b   = (const float*)d_in[7];
    const float* fc2w   = (const float*)d_in[8];
    const float* fc2b   = (const float*)d_in[9];
    const float* fc3w   = (const float*)d_in[10];
    const float* fc3b   = (const float*)d_in[11];
    float* out = (float*)d_out;

    // QKV: grid (M/64, 768/64)
    qkv_gemm<<<dim3(M_TOT / 64, 12), 256>>>(text, emb, ipw, ipb);

    // attention
    const int attn_smem = (KT_ROWS * 65 + KT_ROWS * 64 + QT * 64 + QT * 132) * sizeof(float);
    cudaFuncSetAttribute(attn_kernel, cudaFuncAttributeMaxDynamicSharedMemorySize, attn_smem);
    attn_kernel<<<B_ * H_ * (S_ / QT), 256, attn_smem>>>();

    // out_proj
    proj_gemm<<<dim3(M_TOT / 64, 4), 256>>>(opw, opb);

    // pool
    pool_kernel<<<B_, 256>>>();

    // MLP head
    mlp_kernel<<<1, 256>>>(fc1w, fc1b, fc2w, fc2b, fc3w, fc3b, out);
}

// round 2
// speedup vs baseline: 1.1042x; 1.1042x over previous
#include <cuda_runtime.h>
#include <cuda_bf16.h>

#define B_   8
#define S_   2048
#define E_   256
#define H_   4
#define D_   64
#define M_TOT (B_*S_)
#define QT   8
#define KT_ROWS (QT + 2*64)   // 136
#define KSTR 68               // padded K row stride (words)

// -------- scratch --------
__device__ float g_qkv[3ull * B_ * H_ * S_ * D_];   // [sec][b][h][s][d]
__device__ float g_attn[(size_t)M_TOT * E_];        // [m][e]
__device__ unsigned int g_ctx_u[B_ * E_];           // ordered-uint max

__device__ __forceinline__ unsigned int f2ord(float f) {
    unsigned int u = __float_as_uint(f);
    return (u & 0x80000000u) ? ~u : (u | 0x80000000u);
}
__device__ __forceinline__ float ord2f(unsigned int u) {
    return (u & 0x80000000u) ? __uint_as_float(u & 0x7FFFFFFFu)
                             : __uint_as_float(~u);
}

__global__ void init_ctx() {
    g_ctx_u[blockIdx.x * 256 + threadIdx.x] = 0u;
}

// ======================================================================
// Kernel 1: fused embed-gather + QKV GEMM. M=16384, N=768, K=256.
// BM=128, BN=64, BK=32, 256 thr, 8x4 per thread.
// ======================================================================
__global__ void __launch_bounds__(256) qkv_gemm(const int* __restrict__ text,
                                                const float* __restrict__ emb,
                                                const float* __restrict__ W,
                                                const float* __restrict__ bias) {
    __shared__ float As[32][132];
    __shared__ float Ws[32][68];
    __shared__ int   tok_s[128];

    const int tid = threadIdx.x;
    const int tx = tid & 15, ty = tid >> 4;
    const int m0 = blockIdx.x * 128, n0 = blockIdx.y * 64;

    if (tid < 128) tok_s[tid] = text[m0 + tid];

    float acc[8][4] = {};

    for (int kt = 0; kt < 256; kt += 32) {
        __syncthreads();
        #pragma unroll
        for (int it = 0; it < 4; ++it) {          // A tile: 128 rows x 32k
            int idx = tid + it * 256;
            int row = idx >> 3;
            int c4  = (idx & 7) * 4;
            const float* arow = emb + (size_t)tok_s[row] * 256;
            float4 av = *(const float4*)&arow[kt + c4];
            As[c4+0][row] = av.x; As[c4+1][row] = av.y;
            As[c4+2][row] = av.z; As[c4+3][row] = av.w;
        }
        #pragma unroll
        for (int it = 0; it < 2; ++it) {          // W tile: 64 rows x 32k
            int idx = tid + it * 256;
            int row = idx >> 3;
            int c4  = (idx & 7) * 4;
            float4 wv = *(const float4*)&W[(size_t)(n0 + row) * 256 + kt + c4];
            Ws[c4+0][row] = wv.x; Ws[c4+1][row] = wv.y;
            Ws[c4+2][row] = wv.z; Ws[c4+3][row] = wv.w;
        }
        __syncthreads();
        #pragma unroll
        for (int k = 0; k < 32; ++k) {
            float4 a0 = *(const float4*)&As[k][ty * 8];
            float4 a1 = *(const float4*)&As[k][ty * 8 + 4];
            float4 w  = *(const float4*)&Ws[k][tx * 4];
            float av[8] = {a0.x,a0.y,a0.z,a0.w,a1.x,a1.y,a1.z,a1.w};
            float wv[4] = {w.x,w.y,w.z,w.w};
            #pragma unroll
            for (int i = 0; i < 8; ++i)
                #pragma unroll
                for (int j = 0; j < 4; ++j)
                    acc[i][j] += av[i] * wv[j];
        }
    }

    const int sec = n0 >> 8;
    const int h   = (n0 >> 6) & 3;
    const float scale = (sec == 0) ? 0.125f : 1.0f;
    float4 bb = *(const float4*)&bias[n0 + tx * 4];

    #pragma unroll
    for (int i = 0; i < 8; ++i) {
        int m = m0 + ty * 8 + i;
        int b = m >> 11, s = m & 2047;
        float4 o;
        o.x = (acc[i][0] + bb.x) * scale;
        o.y = (acc[i][1] + bb.y) * scale;
        o.z = (acc[i][2] + bb.z) * scale;
        o.w = (acc[i][3] + bb.w) * scale;
        float* ptr = g_qkv + ((((size_t)sec * B_ + b) * H_ + h) * S_ + s) * 64 + tx * 4;
        *(float4*)ptr = o;
    }
}

// ======================================================================
// Kernel 2: banded attention. 1 block = (b,h, 8 queries) = 8 warps.
// ======================================================================
__global__ void __launch_bounds__(256) attn_kernel() {
    extern __shared__ float smem[];
    float* K_s = smem;                         // [136][68]
    float* V_s = K_s + KT_ROWS * KSTR;         // [136][64]
    float* q_s = V_s + KT_ROWS * 64;           // [8][64]
    float* p_s = q_s + QT * 64;                // [8][132]

    const int nq = S_ / QT;
    const int qt = blockIdx.x % nq;
    const int h  = (blockIdx.x / nq) % H_;
    const int b  = blockIdx.x / (nq * H_);

    const int q0 = qt * QT;
    const int kstart = q0 - 64;

    const float* qb = g_qkv + ((size_t)(b * H_ + h)) * S_ * 64;
    const float* kb = g_qkv + ((size_t)(B_ * H_) + b * H_ + h) * S_ * 64;
    const float* vb = g_qkv + ((size_t)(2 * B_ * H_) + b * H_ + h) * S_ * 64;

    const int tid = threadIdx.x;
    for (int idx = tid; idx < KT_ROWS * 16; idx += 256) {   // float4 granularity
        int row = idx >> 4, d4 = (idx & 15) * 4;
        int kg = kstart + row;
        bool in = (kg >= 0) && (kg < S_);
        float4 kv = in ? *(const float4*)&kb[(size_t)kg * 64 + d4]
                       : make_float4(0.f,0.f,0.f,0.f);
        float4 vv = in ? *(const float4*)&vb[(size_t)kg * 64 + d4]
                       : make_float4(0.f,0.f,0.f,0.f);
        *(float4*)&K_s[row * KSTR + d4] = kv;
        *(float4*)&V_s[row * 64 + d4]   = vv;
    }
    for (int idx = tid; idx < QT * 16; idx += 256) {
        int r = idx >> 4, d4 = (idx & 15) * 4;
        *(float4*)&q_s[r * 64 + d4] = *(const float4*)&qb[(size_t)(q0 + r) * 64 + d4];
    }
    __syncthreads();

    const int w = tid >> 5;
    const int lane = tid & 31;
    const int s = q0 + w;
    const float* qr = q_s + w * 64;

    float sc[5];
    #pragma unroll
    for (int r = 0; r < 5; ++r) {
        int t = lane + 32 * r;
        float a = -3.0e38f;
        if (t <= 128) {
            int j = w + t;
            int kg = kstart + j;
            if (kg >= 0 && kg < S_) {
                const float* kr = K_s + j * KSTR;
                float acc = 0.f;
                #pragma unroll
                for (int d = 0; d < 64; d += 4) {
                    float4 qv = *(const float4*)&qr[d];
                    float4 kv = *(const float4*)&kr[d];
                    acc += qv.x*kv.x + qv.y*kv.y + qv.z*kv.z + qv.w*kv.w;
                }
                a = acc;
            }
        }
        sc[r] = a;
    }
    float mx = sc[0];
    #pragma unroll
    for (int r = 1; r < 5; ++r) mx = fmaxf(mx, sc[r]);
    #pragma unroll
    for (int off = 16; off > 0; off >>= 1)
        mx = fmaxf(mx, __shfl_xor_sync(0xffffffffu, mx, off));
    float sum = 0.f;
    #pragma unroll
    for (int r = 0; r < 5; ++r) { sc[r] = __expf(sc[r] - mx); sum += sc[r]; }
    #pragma unroll
    for (int off = 16; off > 0; off >>= 1)
        sum += __shfl_xor_sync(0xffffffffu, sum, off);
    float inv = 1.0f / sum;
    #pragma unroll
    for (int r = 0; r < 5; ++r) {
        int t = lane + 32 * r;
        if (t <= 128) p_s[w * 132 + t] = sc[r] * inv;
    }
    __syncwarp();

    const int d0 = lane * 2;
    float a0 = 0.f, a1 = 0.f;
    #pragma unroll 8
    for (int t = 0; t < 128; t += 4) {
        float4 p = *(const float4*)&p_s[w * 132 + t];
        float2 v0 = *(const float2*)&V_s[(w + t + 0) * 64 + d0];
        float2 v1 = *(const float2*)&V_s[(w + t + 1) * 64 + d0];
        float2 v2 = *(const float2*)&V_s[(w + t + 2) * 64 + d0];
        float2 v3 = *(const float2*)&V_s[(w + t + 3) * 64 + d0];
        a0 += p.x*v0.x + p.y*v1.x + p.z*v2.x + p.w*v3.x;
        a1 += p.x*v0.y + p.y*v1.y + p.z*v2.y + p.w*v3.y;
    }
    {
        float p = p_s[w * 132 + 128];
        float2 v = *(const float2*)&V_s[(w + 128) * 64 + d0];
        a0 += p * v.x; a1 += p * v.y;
    }
    float2 o = {a0, a1};
    *(float2*)&g_attn[((size_t)(b * S_ + s)) * 256 + h * 64 + d0] = o;
}

// ======================================================================
// Kernel 3: out_proj GEMM + fused max-pool. M=16384, N=256, K=256.
// BM=128, BN=64. No proj output is materialized: only per-(batch,col) max.
// ======================================================================
__global__ void __launch_bounds__(256) proj_pool_gemm(const float* __restrict__ W,
                                                      const float* __restrict__ bias) {
    __shared__ float As[32][132];
    __shared__ float Ws[32][68];
    __shared__ float red[16][68];

    const int tid = threadIdx.x;
    const int tx = tid & 15, ty = tid >> 4;
    const int m0 = blockIdx.x * 128, n0 = blockIdx.y * 64;

    float acc[8][4] = {};

    for (int kt = 0; kt < 256; kt += 32) {
        __syncthreads();
        #pragma unroll
        for (int it = 0; it < 4; ++it) {
            int idx = tid + it * 256;
            int row = idx >> 3;
            int c4  = (idx & 7) * 4;
            float4 av = *(const float4*)&g_attn[(size_t)(m0 + row) * 256 + kt + c4];
            As[c4+0][row] = av.x; As[c4+1][row] = av.y;
            As[c4+2][row] = av.z; As[c4+3][row] = av.w;
        }
        #pragma unroll
        for (int it = 0; it < 2; ++it) {
            int idx = tid + it * 256;
            int row = idx >> 3;
            int c4  = (idx & 7) * 4;
            float4 wv = *(const float4*)&W[(size_t)(n0 + row) * 256 + kt + c4];
            Ws[c4+0][row] = wv.x; Ws[c4+1][row] = wv.y;
            Ws[c4+2][row] = wv.z; Ws[c4+3][row] = wv.w;
        }
        __syncthreads();
        #pragma unroll
        for (int k = 0; k < 32; ++k) {
            float4 a0 = *(const float4*)&As[k][ty * 8];
            float4 a1 = *(const float4*)&As[k][ty * 8 + 4];
            float4 w  = *(const float4*)&Ws[k][tx * 4];
            float av[8] = {a0.x,a0.y,a0.z,a0.w,a1.x,a1.y,a1.z,a1.w};
            float wv[4] = {w.x,w.y,w.z,w.w};
            #pragma unroll
            for (int i = 0; i < 8; ++i)
                #pragma unroll
                for (int j = 0; j < 4; ++j)
                    acc[i][j] += av[i] * wv[j];
        }
    }

    float4 bb = *(const float4*)&bias[n0 + tx * 4];
    float lmax[4] = {-3.0e38f, -3.0e38f, -3.0e38f, -3.0e38f};
    #pragma unroll
    for (int i = 0; i < 8; ++i) {
        lmax[0] = fmaxf(lmax[0], acc[i][0] + bb.x);
        lmax[1] = fmaxf(lmax[1], acc[i][1] + bb.y);
        lmax[2] = fmaxf(lmax[2], acc[i][2] + bb.z);
        lmax[3] = fmaxf(lmax[3], acc[i][3] + bb.w);
    }
    __syncthreads();
    #pragma unroll
    for (int j = 0; j < 4; ++j) red[ty][tx * 4 + j] = lmax[j];
    __syncthreads();

    if (tid < 64) {
        float m = red[0][tid];
        #pragma unroll
        for (int r = 1; r < 16; ++r) m = fmaxf(m, red[r][tid]);
        int b = m0 >> 11;                  // 128-row tile lies in a single batch
        atomicMax(&g_ctx_u[b * 256 + n0 + tid], f2ord(m));
    }
}

// ======================================================================
// Kernel 4: MLP head.
// ======================================================================
__global__ void __launch_bounds__(256) mlp_kernel(const float* __restrict__ fc1w,
                                                  const float* __restrict__ fc1b,
                                                  const float* __restrict__ fc2w,
                                                  const float* __restrict__ fc2b,
                                                  const float* __restrict__ fc3w,
                                                  const float* __restrict__ fc3b,
                                                  float* __restrict__ out) {
    __shared__ float ctx_s[8 * 256];
    __shared__ float h1_s[8 * 512];
    __shared__ float h2_s[8 * 256];
    const int tid = threadIdx.x;

    for (int i = tid; i < 8 * 256; i += 256) ctx_s[i] = ord2f(g_ctx_u[i]);
    __syncthreads();

    for (int i = tid; i < 8 * 512; i += 256) {
        int b = i >> 9, o = i & 511;
        float acc = fc1b[o];
        const float* w = fc1w + (size_t)o * 256;
        const float* x = ctx_s + b * 256;
        #pragma unroll 8
        for (int k = 0; k < 256; ++k) acc += x[k] * w[k];
        h1_s[i] = acc > 0.f ? acc : 0.01f * acc;
    }
    __syncthreads();

    for (int i = tid; i < 8 * 256; i += 256) {
        int b = i >> 8, o = i & 255;
        float acc = fc2b[o];
        const float* w = fc2w + (size_t)o * 512;
        const float* x = h1_s + b * 512;
        #pragma unroll 8
        for (int k = 0; k < 512; ++k) acc += x[k] * w[k];
        h2_s[i] = acc > 0.f ? acc : 0.01f * acc;
    }
    __syncthreads();

    if (tid < 8 * 20) {
        int b = tid / 20, o = tid % 20;
        float acc = fc3b[o];
        const float* w = fc3w + (size_t)o * 256;
        const float* x = h2_s + b * 256;
        #pragma unroll 8
        for (int k = 0; k < 256; ++k) acc += x[k] * w[k];
        out[b * 20 + o] = acc;
    }
}

// ======================================================================
extern "C" void kernel_launch(void* const* d_in, const int* in_sizes, int n_in,
                              void* d_out, int out_size) {
    const int*   text = (const int*)d_in[0];
    const float* emb  = (const float*)d_in[1];
    const float* ipw  = (const float*)d_in[2];
    const float* ipb  = (const float*)d_in[3];
    const float* opw  = (const float*)d_in[4];
    const float* opb  = (const float*)d_in[5];
    const float* fc1w = (const float*)d_in[6];
    const float* fc1b = (const float*)d_in[7];
    const float* fc2w = (const float*)d_in[8];
    const float* fc2b = (const float*)d_in[9];
    const float* fc3w = (const float*)d_in[10];
    const float* fc3b = (const float*)d_in[11];
    float* out = (float*)d_out;

    init_ctx<<<8, 256>>>();

    qkv_gemm<<<dim3(M_TOT / 128, 12), 256>>>(text, emb, ipw, ipb);

    const int attn_smem = (KT_ROWS * KSTR + KT_ROWS * 64 + QT * 64 + QT * 132) * sizeof(float);
    cudaFuncSetAttribute(attn_kernel, cudaFuncAttributeMaxDynamicSharedMemorySize, attn_smem);
    attn_kernel<<<B_ * H_ * (S_ / QT), 256, attn_smem>>>();

    proj_pool_gemm<<<dim3(M_TOT / 128, 4), 256>>>(opw, opb);

    mlp_kernel<<<1, 256>>>(fc1w, fc1b, fc2w, fc2b, fc3w, fc3b, out);
}

// round 3
// speedup vs baseline: 4.0017x; 3.6240x over previous
#include <cuda_runtime.h>
#include <cuda_bf16.h>

#define B_   8
#define S_   2048
#define E_   256
#define H_   4
#define D_   64
#define M_TOT (B_*S_)
#define QT   16
#define AT_THREADS (QT*32)
#define KT_ROWS (QT + 2*64)   // 144
#define KSTR 68               // padded K row stride (words)

// -------- scratch --------
__device__ float g_qkv[3ull * B_ * H_ * S_ * D_];   // [sec][b][h][s][d]
__device__ float g_attn[(size_t)M_TOT * E_];        // [m][e]
__device__ unsigned int g_ctx_u[B_ * E_];           // ordered-uint max
__device__ float g_ctx[B_ * E_];
__device__ float g_h1[B_ * 512];
__device__ float g_h2[B_ * 256];

__device__ __forceinline__ unsigned int f2ord(float f) {
    unsigned int u = __float_as_uint(f);
    return (u & 0x80000000u) ? ~u : (u | 0x80000000u);
}
__device__ __forceinline__ float ord2f(unsigned int u) {
    return (u & 0x80000000u) ? __uint_as_float(u & 0x7FFFFFFFu)
                             : __uint_as_float(~u);
}

__global__ void init_ctx() {
    g_ctx_u[blockIdx.x * 256 + threadIdx.x] = 0u;
}

// ======================================================================
// Kernel 1: fused embed-gather + QKV GEMM. M=16384, N=768, K=256.
// BM=128, BN=64, BK=32, 256 thr, 8x4 per thread.
// ======================================================================
__global__ void __launch_bounds__(256) qkv_gemm(const int* __restrict__ text,
                                                const float* __restrict__ emb,
                                                const float* __restrict__ W,
                                                const float* __restrict__ bias) {
    __shared__ float As[32][132];
    __shared__ float Ws[32][68];
    __shared__ int   tok_s[128];

    const int tid = threadIdx.x;
    const int tx = tid & 15, ty = tid >> 4;
    const int m0 = blockIdx.x * 128, n0 = blockIdx.y * 64;

    if (tid < 128) tok_s[tid] = text[m0 + tid];

    float acc[8][4] = {};

    for (int kt = 0; kt < 256; kt += 32) {
        __syncthreads();
        #pragma unroll
        for (int it = 0; it < 4; ++it) {
            int idx = tid + it * 256;
            int row = idx >> 3;
            int c4  = (idx & 7) * 4;
            const float* arow = emb + (size_t)tok_s[row] * 256;
            float4 av = *(const float4*)&arow[kt + c4];
            As[c4+0][row] = av.x; As[c4+1][row] = av.y;
            As[c4+2][row] = av.z; As[c4+3][row] = av.w;
        }
        #pragma unroll
        for (int it = 0; it < 2; ++it) {
            int idx = tid + it * 256;
            int row = idx >> 3;
            int c4  = (idx & 7) * 4;
            float4 wv = *(const float4*)&W[(size_t)(n0 + row) * 256 + kt + c4];
            Ws[c4+0][row] = wv.x; Ws[c4+1][row] = wv.y;
            Ws[c4+2][row] = wv.z; Ws[c4+3][row] = wv.w;
        }
        __syncthreads();
        #pragma unroll
        for (int k = 0; k < 32; ++k) {
            float4 a0 = *(const float4*)&As[k][ty * 8];
            float4 a1 = *(const float4*)&As[k][ty * 8 + 4];
            float4 w  = *(const float4*)&Ws[k][tx * 4];
            float av[8] = {a0.x,a0.y,a0.z,a0.w,a1.x,a1.y,a1.z,a1.w};
            float wv[4] = {w.x,w.y,w.z,w.w};
            #pragma unroll
            for (int i = 0; i < 8; ++i)
                #pragma unroll
                for (int j = 0; j < 4; ++j)
                    acc[i][j] += av[i] * wv[j];
        }
    }

    const int sec = n0 >> 8;
    const int h   = (n0 >> 6) & 3;
    const float scale = (sec == 0) ? 0.125f : 1.0f;
    float4 bb = *(const float4*)&bias[n0 + tx * 4];

    #pragma unroll
    for (int i = 0; i < 8; ++i) {
        int m = m0 + ty * 8 + i;
        int b = m >> 11, s = m & 2047;
        float4 o;
        o.x = (acc[i][0] + bb.x) * scale;
        o.y = (acc[i][1] + bb.y) * scale;
        o.z = (acc[i][2] + bb.z) * scale;
        o.w = (acc[i][3] + bb.w) * scale;
        float* ptr = g_qkv + ((((size_t)sec * B_ + b) * H_ + h) * S_ + s) * 64 + tx * 4;
        *(float4*)ptr = o;
    }
}

// ======================================================================
// Kernel 2: banded attention. 1 block = (b,h, 16 queries) = 16 warps.
// ======================================================================
__global__ void __launch_bounds__(AT_THREADS) attn_kernel() {
    extern __shared__ float smem[];
    float* K_s = smem;                         // [144][68]
    float* V_s = K_s + KT_ROWS * KSTR;         // [144][64]
    float* q_s = V_s + KT_ROWS * 64;           // [16][64]
    float* p_s = q_s + QT * 64;                // [16][132]

    const int nq = S_ / QT;
    const int qt = blockIdx.x % nq;
    const int h  = (blockIdx.x / nq) % H_;
    const int b  = blockIdx.x / (nq * H_);

    const int q0 = qt * QT;
    const int kstart = q0 - 64;

    const float* qb = g_qkv + ((size_t)(b * H_ + h)) * S_ * 64;
    const float* kb = g_qkv + ((size_t)(B_ * H_) + b * H_ + h) * S_ * 64;
    const float* vb = g_qkv + ((size_t)(2 * B_ * H_) + b * H_ + h) * S_ * 64;

    const int tid = threadIdx.x;
    for (int idx = tid; idx < KT_ROWS * 16; idx += AT_THREADS) {
        int row = idx >> 4, d4 = (idx & 15) * 4;
        int kg = kstart + row;
        bool in = (kg >= 0) && (kg < S_);
        float4 kv = in ? *(const float4*)&kb[(size_t)kg * 64 + d4]
                       : make_float4(0.f,0.f,0.f,0.f);
        float4 vv = in ? *(const float4*)&vb[(size_t)kg * 64 + d4]
                       : make_float4(0.f,0.f,0.f,0.f);
        *(float4*)&K_s[row * KSTR + d4] = kv;
        *(float4*)&V_s[row * 64 + d4]   = vv;
    }
    for (int idx = tid; idx < QT * 16; idx += AT_THREADS) {
        int r = idx >> 4, d4 = (idx & 15) * 4;
        *(float4*)&q_s[r * 64 + d4] = *(const float4*)&qb[(size_t)(q0 + r) * 64 + d4];
    }
    __syncthreads();

    const int w = tid >> 5;      // warp = query
    const int lane = tid & 31;
    const int s = q0 + w;
    const float* qr = q_s + w * 64;

    float sc[5];
    #pragma unroll
    for (int r = 0; r < 5; ++r) {
        int t = lane + 32 * r;
        float a = -3.0e38f;
        if (t <= 128) {
            int j = w + t;
            int kg = kstart + j;
            if (kg >= 0 && kg < S_) {
                const float* kr = K_s + j * KSTR;
                float acc = 0.f;
                #pragma unroll
                for (int d = 0; d < 64; d += 4) {
                    float4 qv = *(const float4*)&qr[d];
                    float4 kv = *(const float4*)&kr[d];
                    acc += qv.x*kv.x + qv.y*kv.y + qv.z*kv.z + qv.w*kv.w;
                }
                a = acc;
            }
        }
        sc[r] = a;
    }
    float mx = sc[0];
    #pragma unroll
    for (int r = 1; r < 5; ++r) mx = fmaxf(mx, sc[r]);
    #pragma unroll
    for (int off = 16; off > 0; off >>= 1)
        mx = fmaxf(mx, __shfl_xor_sync(0xffffffffu, mx, off));
    float sum = 0.f;
    #pragma unroll
    for (int r = 0; r < 5; ++r) { sc[r] = __expf(sc[r] - mx); sum += sc[r]; }
    #pragma unroll
    for (int off = 16; off > 0; off >>= 1)
        sum += __shfl_xor_sync(0xffffffffu, sum, off);
    float inv = 1.0f / sum;
    #pragma unroll
    for (int r = 0; r < 5; ++r) {
        int t = lane + 32 * r;
        if (t <= 128) p_s[w * 132 + t] = sc[r] * inv;
    }
    __syncwarp();

    const int d0 = lane * 2;
    float a0 = 0.f, a1 = 0.f;
    #pragma unroll 8
    for (int t = 0; t < 128; t += 4) {
        float4 p = *(const float4*)&p_s[w * 132 + t];
        float2 v0 = *(const float2*)&V_s[(w + t + 0) * 64 + d0];
        float2 v1 = *(const float2*)&V_s[(w + t + 1) * 64 + d0];
        float2 v2 = *(const float2*)&V_s[(w + t + 2) * 64 + d0];
        float2 v3 = *(const float2*)&V_s[(w + t + 3) * 64 + d0];
        a0 += p.x*v0.x + p.y*v1.x + p.z*v2.x + p.w*v3.x;
        a1 += p.x*v0.y + p.y*v1.y + p.z*v2.y + p.w*v3.y;
    }
    {
        float p = p_s[w * 132 + 128];
        float2 v = *(const float2*)&V_s[(w + 128) * 64 + d0];
        a0 += p * v.x; a1 += p * v.y;
    }
    float2 o = {a0, a1};
    *(float2*)&g_attn[((size_t)(b * S_ + s)) * 256 + h * 64 + d0] = o;
}

// ======================================================================
// Kernel 3: out_proj GEMM + fused max-pool. M=16384, N=256, K=256.
// ======================================================================
__global__ void __launch_bounds__(256) proj_pool_gemm(const float* __restrict__ W,
                                                      const float* __restrict__ bias) {
    __shared__ float As[32][132];
    __shared__ float Ws[32][68];
    __shared__ float red[16][68];

    const int tid = threadIdx.x;
    const int tx = tid & 15, ty = tid >> 4;
    const int m0 = blockIdx.x * 128, n0 = blockIdx.y * 64;

    float acc[8][4] = {};

    for (int kt = 0; kt < 256; kt += 32) {
        __syncthreads();
        #pragma unroll
        for (int it = 0; it < 4; ++it) {
            int idx = tid + it * 256;
            int row = idx >> 3;
            int c4  = (idx & 7) * 4;
            float4 av = *(const float4*)&g_attn[(size_t)(m0 + row) * 256 + kt + c4];
            As[c4+0][row] = av.x; As[c4+1][row] = av.y;
            As[c4+2][row] = av.z; As[c4+3][row] = av.w;
        }
        #pragma unroll
        for (int it = 0; it < 2; ++it) {
            int idx = tid + it * 256;
            int row = idx >> 3;
            int c4  = (idx & 7) * 4;
            float4 wv = *(const float4*)&W[(size_t)(n0 + row) * 256 + kt + c4];
            Ws[c4+0][row] = wv.x; Ws[c4+1][row] = wv.y;
            Ws[c4+2][row] = wv.z; Ws[c4+3][row] = wv.w;
        }
        __syncthreads();
        #pragma unroll
        for (int k = 0; k < 32; ++k) {
            float4 a0 = *(const float4*)&As[k][ty * 8];
            float4 a1 = *(const float4*)&As[k][ty * 8 + 4];
            float4 w  = *(const float4*)&Ws[k][tx * 4];
            float av[8] = {a0.x,a0.y,a0.z,a0.w,a1.x,a1.y,a1.z,a1.w};
            float wv[4] = {w.x,w.y,w.z,w.w};
            #pragma unroll
            for (int i = 0; i < 8; ++i)
                #pragma unroll
                for (int j = 0; j < 4; ++j)
                    acc[i][j] += av[i] * wv[j];
        }
    }

    float4 bb = *(const float4*)&bias[n0 + tx * 4];
    float lmax[4] = {-3.0e38f, -3.0e38f, -3.0e38f, -3.0e38f};
    #pragma unroll
    for (int i = 0; i < 8; ++i) {
        lmax[0] = fmaxf(lmax[0], acc[i][0] + bb.x);
        lmax[1] = fmaxf(lmax[1], acc[i][1] + bb.y);
        lmax[2] = fmaxf(lmax[2], acc[i][2] + bb.z);
        lmax[3] = fmaxf(lmax[3], acc[i][3] + bb.w);
    }
    __syncthreads();
    #pragma unroll
    for (int j = 0; j < 4; ++j) red[ty][tx * 4 + j] = lmax[j];
    __syncthreads();

    if (tid < 64) {
        float m = red[0][tid];
        #pragma unroll
        for (int r = 1; r < 16; ++r) m = fmaxf(m, red[r][tid]);
        int b = m0 >> 11;
        atomicMax(&g_ctx_u[b * 256 + n0 + tid], f2ord(m));
    }
}

// ======================================================================
// Kernel 3b: convert ordered-uint max -> float ctx
// ======================================================================
__global__ void ctx_finalize() {
    int i = blockIdx.x * 256 + threadIdx.x;
    g_ctx[i] = ord2f(g_ctx_u[i]);
}

// ======================================================================
// MLP head: one warp per output neuron, coalesced float4 weight loads.
// ======================================================================
__global__ void __launch_bounds__(256) fc1_kernel(const float* __restrict__ w,
                                                  const float* __restrict__ bias) {
    const int gid = blockIdx.x * 8 + (threadIdx.x >> 5);   // 0..4095
    const int lane = threadIdx.x & 31;
    const int b = gid >> 9, o = gid & 511;
    const float* wr = w + (size_t)o * 256 + lane * 8;
    const float* xr = g_ctx + b * 256 + lane * 8;
    float4 w0 = *(const float4*)wr,       w1 = *(const float4*)(wr + 4);
    float4 x0 = *(const float4*)xr,       x1 = *(const float4*)(xr + 4);
    float acc = w0.x*x0.x + w0.y*x0.y + w0.z*x0.z + w0.w*x0.w
              + w1.x*x1.x + w1.y*x1.y + w1.z*x1.z + w1.w*x1.w;
    #pragma unroll
    for (int off = 16; off > 0; off >>= 1)
        acc += __shfl_xor_sync(0xffffffffu, acc, off);
    if (lane == 0) {
        acc += bias[o];
        g_h1[gid] = acc > 0.f ? acc : 0.01f * acc;
    }
}

__global__ void __launch_bounds__(256) fc2_kernel(const float* __restrict__ w,
                                                  const float* __restrict__ bias) {
    const int gid = blockIdx.x * 8 + (threadIdx.x >> 5);   // 0..2047
    const int lane = threadIdx.x & 31;
    const int b = gid >> 8, o = gid & 255;
    const float* wr = w + (size_t)o * 512 + lane * 16;
    const float* xr = g_h1 + b * 512 + lane * 16;
    float acc = 0.f;
    #pragma unroll
    for (int c = 0; c < 4; ++c) {
        float4 wv = *(const float4*)(wr + c * 4);
        float4 xv = *(const float4*)(xr + c * 4);
        acc += wv.x*xv.x + wv.y*xv.y + wv.z*xv.z + wv.w*xv.w;
    }
    #pragma unroll
    for (int off = 16; off > 0; off >>= 1)
        acc += __shfl_xor_sync(0xffffffffu, acc, off);
    if (lane == 0) {
        acc += bias[o];
        g_h2[gid] = acc > 0.f ? acc : 0.01f * acc;
    }
}

__global__ void __launch_bounds__(256) fc3_kernel(const float* __restrict__ w,
                                                  const float* __restrict__ bias,
                                                  float* __restrict__ out) {
    const int gid = blockIdx.x * 8 + (threadIdx.x >> 5);   // 0..159
    const int lane = threadIdx.x & 31;
    if (gid >= 8 * 20) return;
    const int b = gid / 20, o = gid % 20;
    const float* wr = w + (size_t)o * 256 + lane * 8;
    const float* xr = g_h2 + b * 256 + lane * 8;
    float4 w0 = *(const float4*)wr,       w1 = *(const float4*)(wr + 4);
    float4 x0 = *(const float4*)xr,       x1 = *(const float4*)(xr + 4);
    float acc = w0.x*x0.x + w0.y*x0.y + w0.z*x0.z + w0.w*x0.w
              + w1.x*x1.x + w1.y*x1.y + w1.z*x1.z + w1.w*x1.w;
    #pragma unroll
    for (int off = 16; off > 0; off >>= 1)
        acc += __shfl_xor_sync(0xffffffffu, acc, off);
    if (lane == 0) out[b * 20 + o] = acc + bias[o];
}

// ======================================================================
extern "C" void kernel_launch(void* const* d_in, const int* in_sizes, int n_in,
                              void* d_out, int out_size) {
    const int*   text = (const int*)d_in[0];
    const float* emb  = (const float*)d_in[1];
    const float* ipw  = (const float*)d_in[2];
    const float* ipb  = (const float*)d_in[3];
    const float* opw  = (const float*)d_in[4];
    const float* opb  = (const float*)d_in[5];
    const float* fc1w = (const float*)d_in[6];
    const float* fc1b = (const float*)d_in[7];
    const float* fc2w = (const float*)d_in[8];
    const float* fc2b = (const float*)d_in[9];
    const float* fc3w = (const float*)d_in[10];
    const float* fc3b = (const float*)d_in[11];
    float* out = (float*)d_out;

    init_ctx<<<8, 256>>>();

    qkv_gemm<<<dim3(M_TOT / 128, 12), 256>>>(text, emb, ipw, ipb);

    const int attn_smem = (KT_ROWS * KSTR + KT_ROWS * 64 + QT * 64 + QT * 132) * sizeof(float);
    cudaFuncSetAttribute(attn_kernel, cudaFuncAttributeMaxDynamicSharedMemorySize, attn_smem);
    attn_kernel<<<B_ * H_ * (S_ / QT), AT_THREADS, attn_smem>>>();

    proj_pool_gemm<<<dim3(M_TOT / 128, 4), 256>>>(opw, opb);
    ctx_finalize<<<8, 256>>>();

    fc1_kernel<<<512, 256>>>(fc1w, fc1b);
    fc2_kernel<<<256, 256>>>(fc2w, fc2b);
    fc3_kernel<<<20, 256>>>(fc3w, fc3b, out);
}

// round 4
// speedup vs baseline: 4.2018x; 1.0500x over previous
#include <cuda_runtime.h>
#include <cuda_bf16.h>

#define B_   8
#define S_   2048
#define E_   256
#define H_   4
#define D_   64
#define M_TOT (B_*S_)
#define QT   16
#define AT_THREADS (QT*32)
#define KT_ROWS (QT + 2*64)   // 144
#define KSTR 68               // padded K row stride (words)

// -------- scratch --------
__device__ float g_qkv[3ull * B_ * H_ * S_ * D_];   // [sec][b][h][s][d]
__device__ float g_attn[(size_t)M_TOT * E_];        // [m][e]
__device__ unsigned int g_ctx_u[B_ * E_];
__device__ float g_ctx[B_ * E_];
__device__ float g_h1[B_ * 512];
__device__ float g_h2[B_ * 256];

__device__ __forceinline__ unsigned int f2ord(float f) {
    unsigned int u = __float_as_uint(f);
    return (u & 0x80000000u) ? ~u : (u | 0x80000000u);
}
__device__ __forceinline__ float ord2f(unsigned int u) {
    return (u & 0x80000000u) ? __uint_as_float(u & 0x7FFFFFFFu)
                             : __uint_as_float(~u);
}

__global__ void init_ctx() {
    g_ctx_u[blockIdx.x * 256 + threadIdx.x] = 0u;
}

// ======================================================================
// Kernel 1: fused embed-gather + QKV GEMM. M=16384, N=768, K=256.
// BM=128, BN=128, BK=32, 256 thr, 8x8 per thread (split 4+4 halves).
// ======================================================================
__global__ void __launch_bounds__(256) qkv_gemm(const int* __restrict__ text,
                                                const float* __restrict__ emb,
                                                const float* __restrict__ W,
                                                const float* __restrict__ bias) {
    __shared__ float As[32][132];
    __shared__ float Ws[32][132];
    __shared__ int   tok_s[128];

    const int tid = threadIdx.x;
    const int tx = tid & 15, ty = tid >> 4;
    const int m0 = blockIdx.x * 128, n0 = blockIdx.y * 128;

    if (tid < 128) tok_s[tid] = text[m0 + tid];

    float acc[8][8] = {};

    for (int kt = 0; kt < 256; kt += 32) {
        __syncthreads();
        #pragma unroll
        for (int it = 0; it < 4; ++it) {
            int idx = tid + it * 256;
            int row = idx >> 3;
            int c4  = (idx & 7) * 4;
            float4 av = *(const float4*)&emb[(size_t)tok_s[row] * 256 + kt + c4];
            As[c4+0][row] = av.x; As[c4+1][row] = av.y;
            As[c4+2][row] = av.z; As[c4+3][row] = av.w;
            float4 wv = *(const float4*)&W[(size_t)(n0 + row) * 256 + kt + c4];
            Ws[c4+0][row] = wv.x; Ws[c4+1][row] = wv.y;
            Ws[c4+2][row] = wv.z; Ws[c4+3][row] = wv.w;
        }
        __syncthreads();
        #pragma unroll
        for (int k = 0; k < 32; ++k) {
            float4 a0 = *(const float4*)&As[k][ty * 4];
            float4 a1 = *(const float4*)&As[k][64 + ty * 4];
            float4 w0 = *(const float4*)&Ws[k][tx * 4];
            float4 w1 = *(const float4*)&Ws[k][64 + tx * 4];
            float av[8] = {a0.x,a0.y,a0.z,a0.w,a1.x,a1.y,a1.z,a1.w};
            float wv[8] = {w0.x,w0.y,w0.z,w0.w,w1.x,w1.y,w1.z,w1.w};
            #pragma unroll
            for (int i = 0; i < 8; ++i)
                #pragma unroll
                for (int j = 0; j < 8; ++j)
                    acc[i][j] += av[i] * wv[j];
        }
    }

    #pragma unroll
    for (int cg = 0; cg < 2; ++cg) {
        const int n = n0 + cg * 64 + tx * 4;
        const int sec = n >> 8;
        const int h   = (n >> 6) & 3;
        const float scale = (sec == 0) ? 0.125f : 1.0f;
        float4 bb = *(const float4*)&bias[n];
        #pragma unroll
        for (int rg = 0; rg < 2; ++rg)
            #pragma unroll
            for (int i = 0; i < 4; ++i) {
                int m = m0 + rg * 64 + ty * 4 + i;
                int b = m >> 11, s = m & 2047;
                float4 o;
                o.x = (acc[rg*4+i][cg*4+0] + bb.x) * scale;
                o.y = (acc[rg*4+i][cg*4+1] + bb.y) * scale;
                o.z = (acc[rg*4+i][cg*4+2] + bb.z) * scale;
                o.w = (acc[rg*4+i][cg*4+3] + bb.w) * scale;
                float* ptr = g_qkv + ((((size_t)sec * B_ + b) * H_ + h) * S_ + s) * 64 + (tx * 4);
                *(float4*)ptr = o;
            }
    }
}

// ======================================================================
// Kernel 2: banded attention. 1 block = (b,h, 16 queries) = 16 warps.
// ======================================================================
__global__ void __launch_bounds__(AT_THREADS) attn_kernel() {
    extern __shared__ float smem[];
    float* K_s = smem;                         // [144][68]
    float* V_s = K_s + KT_ROWS * KSTR;         // [144][64]
    float* q_s = V_s + KT_ROWS * 64;           // [16][64]
    float* p_s = q_s + QT * 64;                // [16][132]

    const int nq = S_ / QT;
    const int qt = blockIdx.x % nq;
    const int h  = (blockIdx.x / nq) % H_;
    const int b  = blockIdx.x / (nq * H_);

    const int q0 = qt * QT;
    const int kstart = q0 - 64;

    const float* qb = g_qkv + ((size_t)(b * H_ + h)) * S_ * 64;
    const float* kb = g_qkv + ((size_t)(B_ * H_) + b * H_ + h) * S_ * 64;
    const float* vb = g_qkv + ((size_t)(2 * B_ * H_) + b * H_ + h) * S_ * 64;

    const int tid = threadIdx.x;
    for (int idx = tid; idx < KT_ROWS * 16; idx += AT_THREADS) {
        int row = idx >> 4, d4 = (idx & 15) * 4;
        int kg = kstart + row;
        bool in = (kg >= 0) && (kg < S_);
        float4 kv = in ? *(const float4*)&kb[(size_t)kg * 64 + d4]
                       : make_float4(0.f,0.f,0.f,0.f);
        float4 vv = in ? *(const float4*)&vb[(size_t)kg * 64 + d4]
                       : make_float4(0.f,0.f,0.f,0.f);
        *(float4*)&K_s[row * KSTR + d4] = kv;
        *(float4*)&V_s[row * 64 + d4]   = vv;
    }
    for (int idx = tid; idx < QT * 16; idx += AT_THREADS) {
        int r = idx >> 4, d4 = (idx & 15) * 4;
        *(float4*)&q_s[r * 64 + d4] = *(const float4*)&qb[(size_t)(q0 + r) * 64 + d4];
    }
    __syncthreads();

    const int w = tid >> 5;
    const int lane = tid & 31;
    const int s = q0 + w;
    const float* qr = q_s + w * 64;

    // 5 key groups per lane; q loaded once per d-chunk
    int   jr[5];
    bool  valid[5];
    float sc[5] = {0.f, 0.f, 0.f, 0.f, 0.f};
    #pragma unroll
    for (int r = 0; r < 5; ++r) {
        int t = lane + 32 * r;
        int j = w + t;
        int kg = kstart + j;
        valid[r] = (t <= 128) && (kg >= 0) && (kg < S_);
        jr[r] = (j < KT_ROWS) ? j : 0;     // clamped rows are never used
    }
    #pragma unroll
    for (int d = 0; d < 64; d += 4) {
        float4 qv = *(const float4*)&qr[d];
        #pragma unroll
        for (int r = 0; r < 5; ++r) {
            float4 kv = *(const float4*)&K_s[jr[r] * KSTR + d];
            sc[r] += qv.x*kv.x + qv.y*kv.y + qv.z*kv.z + qv.w*kv.w;
        }
    }
    #pragma unroll
    for (int r = 0; r < 5; ++r) if (!valid[r]) sc[r] = -3.0e38f;

    float mx = sc[0];
    #pragma unroll
    for (int r = 1; r < 5; ++r) mx = fmaxf(mx, sc[r]);
    #pragma unroll
    for (int off = 16; off > 0; off >>= 1)
        mx = fmaxf(mx, __shfl_xor_sync(0xffffffffu, mx, off));
    float sum = 0.f;
    #pragma unroll
    for (int r = 0; r < 5; ++r) { sc[r] = __expf(sc[r] - mx); sum += sc[r]; }
    #pragma unroll
    for (int off = 16; off > 0; off >>= 1)
        sum += __shfl_xor_sync(0xffffffffu, sum, off);
    float inv = 1.0f / sum;
    #pragma unroll
    for (int r = 0; r < 5; ++r) {
        int t = lane + 32 * r;
        if (t <= 128) p_s[w * 132 + t] = sc[r] * inv;
    }
    __syncwarp();

    const int d0 = lane * 2;
    float a0 = 0.f, a1 = 0.f;
    #pragma unroll 8
    for (int t = 0; t < 128; t += 4) {
        float4 p = *(const float4*)&p_s[w * 132 + t];
        float2 v0 = *(const float2*)&V_s[(w + t + 0) * 64 + d0];
        float2 v1 = *(const float2*)&V_s[(w + t + 1) * 64 + d0];
        float2 v2 = *(const float2*)&V_s[(w + t + 2) * 64 + d0];
        float2 v3 = *(const float2*)&V_s[(w + t + 3) * 64 + d0];
        a0 += p.x*v0.x + p.y*v1.x + p.z*v2.x + p.w*v3.x;
        a1 += p.x*v0.y + p.y*v1.y + p.z*v2.y + p.w*v3.y;
    }
    {
        float p = p_s[w * 132 + 128];
        float2 v = *(const float2*)&V_s[(w + 128) * 64 + d0];
        a0 += p * v.x; a1 += p * v.y;
    }
    float2 o = {a0, a1};
    *(float2*)&g_attn[((size_t)(b * S_ + s)) * 256 + h * 64 + d0] = o;
}

// ======================================================================
// Kernel 3: out_proj GEMM + fused max-pool. BM=128, BN=128, 8x8/thr.
// ======================================================================
__global__ void __launch_bounds__(256) proj_pool_gemm(const float* __restrict__ W,
                                                      const float* __restrict__ bias) {
    __shared__ float As[32][132];
    __shared__ float Ws[32][132];
    __shared__ float red[16][132];

    const int tid = threadIdx.x;
    const int tx = tid & 15, ty = tid >> 4;
    const int m0 = blockIdx.x * 128, n0 = blockIdx.y * 128;

    float acc[8][8] = {};

    for (int kt = 0; kt < 256; kt += 32) {
        __syncthreads();
        #pragma unroll
        for (int it = 0; it < 4; ++it) {
            int idx = tid + it * 256;
            int row = idx >> 3;
            int c4  = (idx & 7) * 4;
            float4 av = *(const float4*)&g_attn[(size_t)(m0 + row) * 256 + kt + c4];
            As[c4+0][row] = av.x; As[c4+1][row] = av.y;
            As[c4+2][row] = av.z; As[c4+3][row] = av.w;
            float4 wv = *(const float4*)&W[(size_t)(n0 + row) * 256 + kt + c4];
            Ws[c4+0][row] = wv.x; Ws[c4+1][row] = wv.y;
            Ws[c4+2][row] = wv.z; Ws[c4+3][row] = wv.w;
        }
        __syncthreads();
        #pragma unroll
        for (int k = 0; k < 32; ++k) {
            float4 a0 = *(const float4*)&As[k][ty * 4];
            float4 a1 = *(const float4*)&As[k][64 + ty * 4];
            float4 w0 = *(const float4*)&Ws[k][tx * 4];
            float4 w1 = *(const float4*)&Ws[k][64 + tx * 4];
            float av[8] = {a0.x,a0.y,a0.z,a0.w,a1.x,a1.y,a1.z,a1.w};
            float wv[8] = {w0.x,w0.y,w0.z,w0.w,w1.x,w1.y,w1.z,w1.w};
            #pragma unroll
            for (int i = 0; i < 8; ++i)
                #pragma unroll
                for (int j = 0; j < 8; ++j)
                    acc[i][j] += av[i] * wv[j];
        }
    }

    // fused max over the 8 rows this thread owns, per column
    float lmax[8];
    #pragma unroll
    for (int cg = 0; cg < 2; ++cg) {
        float4 bb = *(const float4*)&bias[n0 + cg * 64 + tx * 4];
        float bbv[4] = {bb.x, bb.y, bb.z, bb.w};
        #pragma unroll
        for (int j = 0; j < 4; ++j) {
            float m = -3.0e38f;
            #pragma unroll
            for (int i = 0; i < 8; ++i)
                m = fmaxf(m, acc[i][cg*4+j] + bbv[j]);
            lmax[cg*4+j] = m;
        }
    }
    __syncthreads();
    #pragma unroll
    for (int cg = 0; cg < 2; ++cg)
        #pragma unroll
        for (int j = 0; j < 4; ++j)
            red[ty][cg * 64 + tx * 4 + j] = lmax[cg*4+j];
    __syncthreads();

    if (tid < 128) {
        float m = red[0][tid];
        #pragma unroll
        for (int r = 1; r < 16; ++r) m = fmaxf(m, red[r][tid]);
        int b = m0 >> 11;
        atomicMax(&g_ctx_u[b * 256 + n0 + tid], f2ord(m));
    }
}

__global__ void ctx_finalize() {
    int i = blockIdx.x * 256 + threadIdx.x;
    g_ctx[i] = ord2f(g_ctx_u[i]);
}

// ======================================================================
// MLP head: one warp per output neuron.
// ======================================================================
__global__ void __launch_bounds__(256) fc1_kernel(const float* __restrict__ w,
                                                  const float* __restrict__ bias) {
    const int gid = blockIdx.x * 8 + (threadIdx.x >> 5);
    const int lane = threadIdx.x & 31;
    const int b = gid >> 9, o = gid & 511;
    const float* wr = w + (size_t)o * 256 + lane * 8;
    const float* xr = g_ctx + b * 256 + lane * 8;
    float4 w0 = *(const float4*)wr,  w1 = *(const float4*)(wr + 4);
    float4 x0 = *(const float4*)xr,  x1 = *(const float4*)(xr + 4);
    float acc = w0.x*x0.x + w0.y*x0.y + w0.z*x0.z + w0.w*x0.w
              + w1.x*x1.x + w1.y*x1.y + w1.z*x1.z + w1.w*x1.w;
    #pragma unroll
    for (int off = 16; off > 0; off >>= 1)
        acc += __shfl_xor_sync(0xffffffffu, acc, off);
    if (lane == 0) {
        acc += bias[o];
        g_h1[gid] = acc > 0.f ? acc : 0.01f * acc;
    }
}

__global__ void __launch_bounds__(256) fc2_kernel(const float* __restrict__ w,
                                                  const float* __restrict__ bias) {
    const int gid = blockIdx.x * 8 + (threadIdx.x >> 5);
    const int lane = threadIdx.x & 31;
    const int b = gid >> 8, o = gid & 255;
    const float* wr = w + (size_t)o * 512 + lane * 16;
    const float* xr = g_h1 + b * 512 + lane * 16;
    float acc = 0.f;
    #pragma unroll
    for (int c = 0; c < 4; ++c) {
        float4 wv = *(const float4*)(wr + c * 4);
        float4 xv = *(const float4*)(xr + c * 4);
        acc += wv.x*xv.x + wv.y*xv.y + wv.z*xv.z + wv.w*xv.w;
    }
    #pragma unroll
    for (int off = 16; off > 0; off >>= 1)
        acc += __shfl_xor_sync(0xffffffffu, acc, off);
    if (lane == 0) {
        acc += bias[o];
        g_h2[gid] = acc > 0.f ? acc : 0.01f * acc;
    }
}

__global__ void __launch_bounds__(256) fc3_kernel(const float* __restrict__ w,
                                                  const float* __restrict__ bias,
                                                  float* __restrict__ out) {
    const int gid = blockIdx.x * 8 + (threadIdx.x >> 5);
    const int lane = threadIdx.x & 31;
    if (gid >= 8 * 20) return;
    const int b = gid / 20, o = gid % 20;
    const float* wr = w + (size_t)o * 256 + lane * 8;
    const float* xr = g_h2 + b * 256 + lane * 8;
    float4 w0 = *(const float4*)wr,  w1 = *(const float4*)(wr + 4);
    float4 x0 = *(const float4*)xr,  x1 = *(const float4*)(xr + 4);
    float acc = w0.x*x0.x + w0.y*x0.y + w0.z*x0.z + w0.w*x0.w
              + w1.x*x1.x + w1.y*x1.y + w1.z*x1.z + w1.w*x1.w;
    #pragma unroll
    for (int off = 16; off > 0; off >>= 1)
        acc += __shfl_xor_sync(0xffffffffu, acc, off);
    if (lane == 0) out[b * 20 + o] = acc + bias[o];
}

// ======================================================================
extern "C" void kernel_launch(void* const* d_in, const int* in_sizes, int n_in,
                              void* d_out, int out_size) {
    const int*   text = (const int*)d_in[0];
    const float* emb  = (const float*)d_in[1];
    const float* ipw  = (const float*)d_in[2];
    const float* ipb  = (const float*)d_in[3];
    const float* opw  = (const float*)d_in[4];
    const float* opb  = (const float*)d_in[5];
    const float* fc1w = (const float*)d_in[6];
    const float* fc1b = (const float*)d_in[7];
    const float* fc2w = (const float*)d_in[8];
    const float* fc2b = (const float*)d_in[9];
    const float* fc3w = (const float*)d_in[10];
    const float* fc3b = (const float*)d_in[11];
    float* out = (float*)d_out;

    init_ctx<<<8, 256>>>();

    qkv_gemm<<<dim3(M_TOT / 128, 6), 256>>>(text, emb, ipw, ipb);

    const int attn_smem = (KT_ROWS * KSTR + KT_ROWS * 64 + QT * 64 + QT * 132) * sizeof(float);
    cudaFuncSetAttribute(attn_kernel, cudaFuncAttributeMaxDynamicSharedMemorySize, attn_smem);
    attn_kernel<<<B_ * H_ * (S_ / QT), AT_THREADS, attn_smem>>>();

    proj_pool_gemm<<<dim3(M_TOT / 128, 2), 256>>>(opw, opb);
    ctx_finalize<<<8, 256>>>();

    fc1_kernel<<<512, 256>>>(fc1w, fc1b);
    fc2_kernel<<<256, 256>>>(fc2w, fc2b);
    fc3_kernel<<<20, 256>>>(fc3w, fc3b, out);
}

// round 5
// speedup vs baseline: 4.3120x; 1.0262x over previous
#include <cuda_runtime.h>
#include <cuda_bf16.h>

#define B_   8
#define S_   2048
#define E_   256
#define H_   4
#define D_   64
#define M_TOT (B_*S_)
#define QT   16
#define AT_THREADS (QT*32)
#define KT_ROWS (QT + 2*64)   // 144
#define KSTR 68               // padded K row stride (words)

typedef unsigned long long u64;

// packed fp32x2 FMA (sm_103a FFMA2): d.lo += a.lo*b.lo; d.hi += a.hi*b.hi
#define FMA2(d, a, b) asm("fma.rn.f32x2 %0, %1, %2, %0;" : "+l"(d) : "l"(a), "l"(b))
#define PACK2(o, x)   asm("mov.b64 %0, {%1, %1};" : "=l"(o) : "f"(x))
#define UNPACK2(lo, hi, v) asm("mov.b64 {%0, %1}, %2;" : "=f"(lo), "=f"(hi) : "l"(v))

// -------- scratch --------
__device__ float g_qkv[3ull * B_ * H_ * S_ * D_];   // [sec][b][h][s][d]
__device__ float g_attn[(size_t)M_TOT * E_];        // [m][e]
__device__ unsigned int g_ctx_u[B_ * E_];
__device__ float g_ctx[B_ * E_];
__device__ float g_h1[B_ * 512];
__device__ float g_h2[B_ * 256];

__device__ __forceinline__ unsigned int f2ord(float f) {
    unsigned int u = __float_as_uint(f);
    return (u & 0x80000000u) ? ~u : (u | 0x80000000u);
}
__device__ __forceinline__ float ord2f(unsigned int u) {
    return (u & 0x80000000u) ? __uint_as_float(u & 0x7FFFFFFFu)
                             : __uint_as_float(~u);
}

__global__ void init_ctx() {
    g_ctx_u[blockIdx.x * 256 + threadIdx.x] = 0u;
}

// ======================================================================
// Kernel 1: fused embed-gather + QKV GEMM. M=16384, N=768, K=256.
// BM=128, BN=128, BK=32, 256 thr, 8x8 per thread via FFMA2 (8x4 pairs).
// ======================================================================
__global__ void __launch_bounds__(256) qkv_gemm(const int* __restrict__ text,
                                                const float* __restrict__ emb,
                                                const float* __restrict__ W,
                                                const float* __restrict__ bias) {
    __shared__ float As[32][132];
    __shared__ float Ws[32][132];
    __shared__ int   tok_s[128];

    const int tid = threadIdx.x;
    const int tx = tid & 15, ty = tid >> 4;
    const int m0 = blockIdx.x * 128, n0 = blockIdx.y * 128;

    if (tid < 128) tok_s[tid] = text[m0 + tid];

    u64 acc2[8][4] = {};

    for (int kt = 0; kt < 256; kt += 32) {
        __syncthreads();
        #pragma unroll
        for (int it = 0; it < 4; ++it) {
            int idx = tid + it * 256;
            int row = idx >> 3;
            int c4  = (idx & 7) * 4;
            float4 av = *(const float4*)&emb[(size_t)tok_s[row] * 256 + kt + c4];
            As[c4+0][row] = av.x; As[c4+1][row] = av.y;
            As[c4+2][row] = av.z; As[c4+3][row] = av.w;
            float4 wv = *(const float4*)&W[(size_t)(n0 + row) * 256 + kt + c4];
            Ws[c4+0][row] = wv.x; Ws[c4+1][row] = wv.y;
            Ws[c4+2][row] = wv.z; Ws[c4+3][row] = wv.w;
        }
        __syncthreads();
        #pragma unroll
        for (int k = 0; k < 32; ++k) {
            float4 a0 = *(const float4*)&As[k][ty * 4];
            float4 a1 = *(const float4*)&As[k][64 + ty * 4];
            ulonglong2 wp0 = *(const ulonglong2*)&Ws[k][tx * 4];
            ulonglong2 wp1 = *(const ulonglong2*)&Ws[k][64 + tx * 4];
            u64 wv[4] = {wp0.x, wp0.y, wp1.x, wp1.y};
            float av[8] = {a0.x,a0.y,a0.z,a0.w,a1.x,a1.y,a1.z,a1.w};
            u64 ap[8];
            #pragma unroll
            for (int i = 0; i < 8; ++i) PACK2(ap[i], av[i]);
            #pragma unroll
            for (int i = 0; i < 8; ++i)
                #pragma unroll
                for (int j = 0; j < 4; ++j)
                    FMA2(acc2[i][j], ap[i], wv[j]);
        }
    }

    float acc[8][8];
    #pragma unroll
    for (int i = 0; i < 8; ++i)
        #pragma unroll
        for (int j = 0; j < 4; ++j)
            UNPACK2(acc[i][j*2], acc[i][j*2+1], acc2[i][j]);

    #pragma unroll
    for (int cg = 0; cg < 2; ++cg) {
        const int n = n0 + cg * 64 + tx * 4;
        const int sec = n >> 8;
        const int h   = (n >> 6) & 3;
        const float scale = (sec == 0) ? 0.125f : 1.0f;
        float4 bb = *(const float4*)&bias[n];
        #pragma unroll
        for (int rg = 0; rg < 2; ++rg)
            #pragma unroll
            for (int i = 0; i < 4; ++i) {
                int m = m0 + rg * 64 + ty * 4 + i;
                int b = m >> 11, s = m & 2047;
                float4 o;
                o.x = (acc[rg*4+i][cg*4+0] + bb.x) * scale;
                o.y = (acc[rg*4+i][cg*4+1] + bb.y) * scale;
                o.z = (acc[rg*4+i][cg*4+2] + bb.z) * scale;
                o.w = (acc[rg*4+i][cg*4+3] + bb.w) * scale;
                float* ptr = g_qkv + ((((size_t)sec * B_ + b) * H_ + h) * S_ + s) * 64 + (tx * 4);
                *(float4*)ptr = o;
            }
    }
}

// ======================================================================
// Kernel 2: banded attention. 1 block = (b,h, 16 queries) = 16 warps.
// ======================================================================
__global__ void __launch_bounds__(AT_THREADS) attn_kernel() {
    extern __shared__ float smem[];
    float* K_s = smem;                         // [144][68]
    float* V_s = K_s + KT_ROWS * KSTR;         // [144][64]
    float* q_s = V_s + KT_ROWS * 64;           // [16][64]
    float* p_s = q_s + QT * 64;                // [16][132]

    const int nq = S_ / QT;
    const int qt = blockIdx.x % nq;
    const int h  = (blockIdx.x / nq) % H_;
    const int b  = blockIdx.x / (nq * H_);

    const int q0 = qt * QT;
    const int kstart = q0 - 64;

    const float* qb = g_qkv + ((size_t)(b * H_ + h)) * S_ * 64;
    const float* kb = g_qkv + ((size_t)(B_ * H_) + b * H_ + h) * S_ * 64;
    const float* vb = g_qkv + ((size_t)(2 * B_ * H_) + b * H_ + h) * S_ * 64;

    const int tid = threadIdx.x;
    for (int idx = tid; idx < KT_ROWS * 16; idx += AT_THREADS) {
        int row = idx >> 4, d4 = (idx & 15) * 4;
        int kg = kstart + row;
        bool in = (kg >= 0) && (kg < S_);
        float4 kv = in ? *(const float4*)&kb[(size_t)kg * 64 + d4]
                       : make_float4(0.f,0.f,0.f,0.f);
        float4 vv = in ? *(const float4*)&vb[(size_t)kg * 64 + d4]
                       : make_float4(0.f,0.f,0.f,0.f);
        *(float4*)&K_s[row * KSTR + d4] = kv;
        *(float4*)&V_s[row * 64 + d4]   = vv;
    }
    for (int idx = tid; idx < QT * 16; idx += AT_THREADS) {
        int r = idx >> 4, d4 = (idx & 15) * 4;
        *(float4*)&q_s[r * 64 + d4] = *(const float4*)&qb[(size_t)(q0 + r) * 64 + d4];
    }
    __syncthreads();

    const int w = tid >> 5;
    const int lane = tid & 31;
    const int s = q0 + w;
    const float* qr = q_s + w * 64;

    int   jr[5];
    bool  valid[5];
    u64   sc2[5] = {0, 0, 0, 0, 0};
    #pragma unroll
    for (int r = 0; r < 5; ++r) {
        int t = lane + 32 * r;
        int j = w + t;
        int kg = kstart + j;
        valid[r] = (t <= 128) && (kg >= 0) && (kg < S_);
        jr[r] = (j < KT_ROWS) ? j : 0;
    }
    #pragma unroll
    for (int d = 0; d < 64; d += 4) {
        ulonglong2 qp = *(const ulonglong2*)&qr[d];
        #pragma unroll
        for (int r = 0; r < 5; ++r) {
            ulonglong2 kp = *(const ulonglong2*)&K_s[jr[r] * KSTR + d];
            FMA2(sc2[r], qp.x, kp.x);
            FMA2(sc2[r], qp.y, kp.y);
        }
    }
    float sc[5];
    #pragma unroll
    for (int r = 0; r < 5; ++r) {
        float lo, hi;
        UNPACK2(lo, hi, sc2[r]);
        sc[r] = valid[r] ? (lo + hi) : -3.0e38f;
    }

    float mx = sc[0];
    #pragma unroll
    for (int r = 1; r < 5; ++r) mx = fmaxf(mx, sc[r]);
    #pragma unroll
    for (int off = 16; off > 0; off >>= 1)
        mx = fmaxf(mx, __shfl_xor_sync(0xffffffffu, mx, off));
    float sum = 0.f;
    #pragma unroll
    for (int r = 0; r < 5; ++r) { sc[r] = __expf(sc[r] - mx); sum += sc[r]; }
    #pragma unroll
    for (int off = 16; off > 0; off >>= 1)
        sum += __shfl_xor_sync(0xffffffffu, sum, off);
    float inv = 1.0f / sum;
    #pragma unroll
    for (int r = 0; r < 5; ++r) {
        int t = lane + 32 * r;
        if (t <= 128) p_s[w * 132 + t] = sc[r] * inv;
    }
    __syncwarp();

    // output: lane owns dims (d0, d0+1) packed in one f32x2 accumulator
    const int d0 = lane * 2;
    u64 acc2 = 0;
    #pragma unroll 8
    for (int t = 0; t < 128; t += 4) {
        float4 p = *(const float4*)&p_s[w * 132 + t];
        u64 v0 = *(const u64*)&V_s[(w + t + 0) * 64 + d0];
        u64 v1 = *(const u64*)&V_s[(w + t + 1) * 64 + d0];
        u64 v2 = *(const u64*)&V_s[(w + t + 2) * 64 + d0];
        u64 v3 = *(const u64*)&V_s[(w + t + 3) * 64 + d0];
        u64 p0, p1, p2, p3;
        PACK2(p0, p.x); PACK2(p1, p.y); PACK2(p2, p.z); PACK2(p3, p.w);
        FMA2(acc2, p0, v0);
        FMA2(acc2, p1, v1);
        FMA2(acc2, p2, v2);
        FMA2(acc2, p3, v3);
    }
    {
        float p = p_s[w * 132 + 128];
        u64 v = *(const u64*)&V_s[(w + 128) * 64 + d0];
        u64 pp; PACK2(pp, p);
        FMA2(acc2, pp, v);
    }
    float a0, a1;
    UNPACK2(a0, a1, acc2);
    float2 o = {a0, a1};
    *(float2*)&g_attn[((size_t)(b * S_ + s)) * 256 + h * 64 + d0] = o;
}

// ======================================================================
// Kernel 3: out_proj GEMM + fused max-pool. BM=128, BN=128, FFMA2.
// ======================================================================
__global__ void __launch_bounds__(256) proj_pool_gemm(const float* __restrict__ W,
                                                      const float* __restrict__ bias) {
    __shared__ float As[32][132];
    __shared__ float Ws[32][132];
    __shared__ float red[16][132];

    const int tid = threadIdx.x;
    const int tx = tid & 15, ty = tid >> 4;
    const int m0 = blockIdx.x * 128, n0 = blockIdx.y * 128;

    u64 acc2[8][4] = {};

    for (int kt = 0; kt < 256; kt += 32) {
        __syncthreads();
        #pragma unroll
        for (int it = 0; it < 4; ++it) {
            int idx = tid + it * 256;
            int row = idx >> 3;
            int c4  = (idx & 7) * 4;
            float4 av = *(const float4*)&g_attn[(size_t)(m0 + row) * 256 + kt + c4];
            As[c4+0][row] = av.x; As[c4+1][row] = av.y;
            As[c4+2][row] = av.z; As[c4+3][row] = av.w;
            float4 wv = *(const float4*)&W[(size_t)(n0 + row) * 256 + kt + c4];
            Ws[c4+0][row] = wv.x; Ws[c4+1][row] = wv.y;
            Ws[c4+2][row] = wv.z; Ws[c4+3][row] = wv.w;
        }
        __syncthreads();
        #pragma unroll
        for (int k = 0; k < 32; ++k) {
            float4 a0 = *(const float4*)&As[k][ty * 4];
            float4 a1 = *(const float4*)&As[k][64 + ty * 4];
            ulonglong2 wp0 = *(const ulonglong2*)&Ws[k][tx * 4];
            ulonglong2 wp1 = *(const ulonglong2*)&Ws[k][64 + tx * 4];
            u64 wv[4] = {wp0.x, wp0.y, wp1.x, wp1.y};
            float av[8] = {a0.x,a0.y,a0.z,a0.w,a1.x,a1.y,a1.z,a1.w};
            u64 ap[8];
            #pragma unroll
            for (int i = 0; i < 8; ++i) PACK2(ap[i], av[i]);
            #pragma unroll
            for (int i = 0; i < 8; ++i)
                #pragma unroll
                for (int j = 0; j < 4; ++j)
                    FMA2(acc2[i][j], ap[i], wv[j]);
        }
    }

    float acc[8][8];
    #pragma unroll
    for (int i = 0; i < 8; ++i)
        #pragma unroll
        for (int j = 0; j < 4; ++j)
            UNPACK2(acc[i][j*2], acc[i][j*2+1], acc2[i][j]);

    float lmax[8];
    #pragma unroll
    for (int cg = 0; cg < 2; ++cg) {
        float4 bb = *(const float4*)&bias[n0 + cg * 64 + tx * 4];
        float bbv[4] = {bb.x, bb.y, bb.z, bb.w};
        #pragma unroll
        for (int j = 0; j < 4; ++j) {
            float m = -3.0e38f;
            #pragma unroll
            for (int i = 0; i < 8; ++i)
                m = fmaxf(m, acc[i][cg*4+j] + bbv[j]);
            lmax[cg*4+j] = m;
        }
    }
    __syncthreads();
    #pragma unroll
    for (int cg = 0; cg < 2; ++cg)
        #pragma unroll
        for (int j = 0; j < 4; ++j)
            red[ty][cg * 64 + tx * 4 + j] = lmax[cg*4+j];
    __syncthreads();

    if (tid < 128) {
        float m = red[0][tid];
        #pragma unroll
        for (int r = 1; r < 16; ++r) m = fmaxf(m, red[r][tid]);
        int b = m0 >> 11;
        atomicMax(&g_ctx_u[b * 256 + n0 + tid], f2ord(m));
    }
}

__global__ void ctx_finalize() {
    int i = blockIdx.x * 256 + threadIdx.x;
    g_ctx[i] = ord2f(g_ctx_u[i]);
}

// ======================================================================
// MLP head: one warp per output neuron.
// ======================================================================
__global__ void __launch_bounds__(256) fc1_kernel(const float* __restrict__ w,
                                                  const float* __restrict__ bias) {
    const int gid = blockIdx.x * 8 + (threadIdx.x >> 5);
    const int lane = threadIdx.x & 31;
    const int b = gid >> 9, o = gid & 511;
    const float* wr = w + (size_t)o * 256 + lane * 8;
    const float* xr = g_ctx + b * 256 + lane * 8;
    float4 w0 = *(const float4*)wr,  w1 = *(const float4*)(wr + 4);
    float4 x0 = *(const float4*)xr,  x1 = *(const float4*)(xr + 4);
    float acc = w0.x*x0.x + w0.y*x0.y + w0.z*x0.z + w0.w*x0.w
              + w1.x*x1.x + w1.y*x1.y + w1.z*x1.z + w1.w*x1.w;
    #pragma unroll
    for (int off = 16; off > 0; off >>= 1)
        acc += __shfl_xor_sync(0xffffffffu, acc, off);
    if (lane == 0) {
        acc += bias[o];
        g_h1[gid] = acc > 0.f ? acc : 0.01f * acc;
    }
}

__global__ void __launch_bounds__(256) fc2_kernel(const float* __restrict__ w,
                                                  const float* __restrict__ bias) {
    const int gid = blockIdx.x * 8 + (threadIdx.x >> 5);
    const int lane = threadIdx.x & 31;
    const int b = gid >> 8, o = gid & 255;
    const float* wr = w + (size_t)o * 512 + lane * 16;
    const float* xr = g_h1 + b * 512 + lane * 16;
    float acc = 0.f;
    #pragma unroll
    for (int c = 0; c < 4; ++c) {
        float4 wv = *(const float4*)(wr + c * 4);
        float4 xv = *(const float4*)(xr + c * 4);
        acc += wv.x*xv.x + wv.y*xv.y + wv.z*xv.z + wv.w*xv.w;
    }
    #pragma unroll
    for (int off = 16; off > 0; off >>= 1)
        acc += __shfl_xor_sync(0xffffffffu, acc, off);
    if (lane == 0) {
        acc += bias[o];
        g_h2[gid] = acc > 0.f ? acc : 0.01f * acc;
    }
}

__global__ void __launch_bounds__(256) fc3_kernel(const float* __restrict__ w,
                                                  const float* __restrict__ bias,
                                                  float* __restrict__ out) {
    const int gid = blockIdx.x * 8 + (threadIdx.x >> 5);
    const int lane = threadIdx.x & 31;
    if (gid >= 8 * 20) return;
    const int b = gid / 20, o = gid % 20;
    const float* wr = w + (size_t)o * 256 + lane * 8;
    const float* xr = g_h2 + b * 256 + lane * 8;
    float4 w0 = *(const float4*)wr,  w1 = *(const float4*)(wr + 4);
    float4 x0 = *(const float4*)xr,  x1 = *(const float4*)(xr + 4);
    float acc = w0.x*x0.x + w0.y*x0.y + w0.z*x0.z + w0.w*x0.w
              + w1.x*x1.x + w1.y*x1.y + w1.z*x1.z + w1.w*x1.w;
    #pragma unroll
    for (int off = 16; off > 0; off >>= 1)
        acc += __shfl_xor_sync(0xffffffffu, acc, off);
    if (lane == 0) out[b * 20 + o] = acc + bias[o];
}

// ======================================================================
extern "C" void kernel_launch(void* const* d_in, const int* in_sizes, int n_in,
                              void* d_out, int out_size) {
    const int*   text = (const int*)d_in[0];
    const float* emb  = (const float*)d_in[1];
    const float* ipw  = (const float*)d_in[2];
    const float* ipb  = (const float*)d_in[3];
    const float* opw  = (const float*)d_in[4];
    const float* opb  = (const float*)d_in[5];
    const float* fc1w = (const float*)d_in[6];
    const float* fc1b = (const float*)d_in[7];
    const float* fc2w = (const float*)d_in[8];
    const float* fc2b = (const float*)d_in[9];
    const float* fc3w = (const float*)d_in[10];
    const float* fc3b = (const float*)d_in[11];
    float* out = (float*)d_out;

    init_ctx<<<8, 256>>>();

    qkv_gemm<<<dim3(M_TOT / 128, 6), 256>>>(text, emb, ipw, ipb);

    const int attn_smem = (KT_ROWS * KSTR + KT_ROWS * 64 + QT * 64 + QT * 132) * sizeof(float);
    cudaFuncSetAttribute(attn_kernel, cudaFuncAttributeMaxDynamicSharedMemorySize, attn_smem);
    attn_kernel<<<B_ * H_ * (S_ / QT), AT_THREADS, attn_smem>>>();

    proj_pool_gemm<<<dim3(M_TOT / 128, 2), 256>>>(opw, opb);
    ctx_finalize<<<8, 256>>>();

    fc1_kernel<<<512, 256>>>(fc1w, fc1b);
    fc2_kernel<<<256, 256>>>(fc2w, fc2b);
    fc3_kernel<<<20, 256>>>(fc3w, fc3b, out);
}

// round 6
// speedup vs baseline: 6.0032x; 1.3922x over previous
#include <cuda_runtime.h>
#include <cuda_bf16.h>

#define B_   8
#define S_   2048
#define E_   256
#define H_   4
#define D_   64
#define M_TOT (B_*S_)
#define QT   16
#define AT_THREADS (QT*32)
#define KT_ROWS (QT + 2*64)   // 144
#define KSTR 68               // padded K row stride (words)

typedef unsigned long long u64;

// packed fp32x2 FMA (sm_103a FFMA2)
#define FMA2(d, a, b) asm("fma.rn.f32x2 %0, %1, %2, %0;" : "+l"(d) : "l"(a), "l"(b))
#define PACK2(o, x)   asm("mov.b64 %0, {%1, %1};" : "=l"(o) : "f"(x))
#define UNPACK2(lo, hi, v) asm("mov.b64 {%0, %1}, %2;" : "=f"(lo), "=f"(hi) : "l"(v))

// tf32 helpers
#define TF32(o, x) asm("cvt.rna.tf32.f32 %0, %1;" : "=r"(o) : "f"(x))
#define MMA_TF32(c, a, b) \
    asm("mma.sync.aligned.m16n8k8.row.col.f32.tf32.tf32.f32 " \
        "{%0,%1,%2,%3}, {%4,%5,%6,%7}, {%8,%9}, {%0,%1,%2,%3};" \
        : "+f"((c).x), "+f"((c).y), "+f"((c).z), "+f"((c).w) \
        : "r"((a)[0]), "r"((a)[1]), "r"((a)[2]), "r"((a)[3]), \
          "r"((b)[0]), "r"((b)[1]))

#define ASTR 36   // smem stride (words) => fragment bank = lane id (conflict-free)

// -------- scratch --------
__device__ float g_qkv[3ull * B_ * H_ * S_ * D_];   // [sec][b][h][s][d]
__device__ float g_attn[(size_t)M_TOT * E_];        // [m][e]
__device__ unsigned int g_ctx_u[B_ * E_];
__device__ float g_ctx[B_ * E_];
__device__ float g_h1[B_ * 512];
__device__ float g_h2[B_ * 256];

__device__ __forceinline__ unsigned int f2ord(float f) {
    unsigned int u = __float_as_uint(f);
    return (u & 0x80000000u) ? ~u : (u | 0x80000000u);
}
__device__ __forceinline__ float ord2f(unsigned int u) {
    return (u & 0x80000000u) ? __uint_as_float(u & 0x7FFFFFFFu)
                             : __uint_as_float(~u);
}

__global__ void init_ctx() {
    g_ctx_u[blockIdx.x * 256 + threadIdx.x] = 0u;
}

// ======================================================================
// Kernel 1: fused embed-gather + QKV GEMM via tf32 MMA.
// M=16384, N=768, K=256. BM=BN=128, BK=32. 8 warps (4x2), warp tile 32x64.
// ======================================================================
__global__ void __launch_bounds__(256) qkv_gemm(const int* __restrict__ text,
                                                const float* __restrict__ emb,
                                                const float* __restrict__ W,
                                                const float* __restrict__ bias) {
    __shared__ unsigned As[128 * ASTR];
    __shared__ unsigned Ws[128 * ASTR];
    __shared__ int tok_s[128];

    const int tid = threadIdx.x;
    const int wid = tid >> 5, lane = tid & 31;
    const int wm = wid & 3, wn = wid >> 2;
    const int qr = lane >> 2, qc = lane & 3;
    const int m0 = blockIdx.x * 128, n0 = blockIdx.y * 128;

    if (tid < 128) tok_s[tid] = text[m0 + tid];

    float4 c[2][8] = {};

    for (int kt = 0; kt < 256; kt += 32) {
        __syncthreads();
        #pragma unroll
        for (int it = 0; it < 4; ++it) {
            int idx = tid + it * 256;
            int row = idx >> 3;
            int c4  = (idx & 7) * 4;
            float4 av = *(const float4*)&emb[(size_t)tok_s[row] * 256 + kt + c4];
            unsigned u0,u1,u2,u3;
            TF32(u0, av.x); TF32(u1, av.y); TF32(u2, av.z); TF32(u3, av.w);
            *(uint4*)&As[row * ASTR + c4] = make_uint4(u0,u1,u2,u3);
            float4 wv = *(const float4*)&W[(size_t)(n0 + row) * 256 + kt + c4];
            TF32(u0, wv.x); TF32(u1, wv.y); TF32(u2, wv.z); TF32(u3, wv.w);
            *(uint4*)&Ws[row * ASTR + c4] = make_uint4(u0,u1,u2,u3);
        }
        __syncthreads();
        #pragma unroll
        for (int ks = 0; ks < 4; ++ks) {
            const int k0 = ks * 8;
            unsigned a[2][4], b[8][2];
            #pragma unroll
            for (int mt = 0; mt < 2; ++mt) {
                int rb = wm * 32 + mt * 16 + qr;
                a[mt][0] = As[(rb    ) * ASTR + k0 + qc];
                a[mt][1] = As[(rb + 8) * ASTR + k0 + qc];
                a[mt][2] = As[(rb    ) * ASTR + k0 + qc + 4];
                a[mt][3] = As[(rb + 8) * ASTR + k0 + qc + 4];
            }
            #pragma unroll
            for (int nt = 0; nt < 8; ++nt) {
                int nb = wn * 64 + nt * 8 + qr;
                b[nt][0] = Ws[nb * ASTR + k0 + qc];
                b[nt][1] = Ws[nb * ASTR + k0 + qc + 4];
            }
            #pragma unroll
            for (int mt = 0; mt < 2; ++mt)
                #pragma unroll
                for (int nt = 0; nt < 8; ++nt)
                    MMA_TF32(c[mt][nt], a[mt], b[nt]);
        }
    }

    #pragma unroll
    for (int nt = 0; nt < 8; ++nt) {
        const int n_g = n0 + wn * 64 + nt * 8 + 2 * qc;
        const int sec = n_g >> 8;
        const int h   = (n_g >> 6) & 3;
        const int d   = n_g & 63;
        const float scale = (sec == 0) ? 0.125f : 1.0f;
        const float b0v = bias[n_g], b1v = bias[n_g + 1];
        #pragma unroll
        for (int mt = 0; mt < 2; ++mt) {
            float4 cc = c[mt][nt];
            int r = wm * 32 + mt * 16 + qr;
            #pragma unroll
            for (int half = 0; half < 2; ++half) {
                int m = m0 + r + half * 8;
                int bb = m >> 11, s = m & 2047;
                float2 o;
                o.x = ((half ? cc.z : cc.x) + b0v) * scale;
                o.y = ((half ? cc.w : cc.y) + b1v) * scale;
                *(float2*)&g_qkv[((((size_t)sec * B_ + bb) * H_ + h) * S_ + s) * 64 + d] = o;
            }
        }
    }
}

// ======================================================================
// Kernel 2: banded attention (unchanged from R5).
// ======================================================================
__global__ void __launch_bounds__(AT_THREADS) attn_kernel() {
    extern __shared__ float smem[];
    float* K_s = smem;                         // [144][68]
    float* V_s = K_s + KT_ROWS * KSTR;         // [144][64]
    float* q_s = V_s + KT_ROWS * 64;           // [16][64]
    float* p_s = q_s + QT * 64;                // [16][132]

    const int nq = S_ / QT;
    const int qt = blockIdx.x % nq;
    const int h  = (blockIdx.x / nq) % H_;
    const int b  = blockIdx.x / (nq * H_);

    const int q0 = qt * QT;
    const int kstart = q0 - 64;

    const float* qb = g_qkv + ((size_t)(b * H_ + h)) * S_ * 64;
    const float* kb = g_qkv + ((size_t)(B_ * H_) + b * H_ + h) * S_ * 64;
    const float* vb = g_qkv + ((size_t)(2 * B_ * H_) + b * H_ + h) * S_ * 64;

    const int tid = threadIdx.x;
    for (int idx = tid; idx < KT_ROWS * 16; idx += AT_THREADS) {
        int row = idx >> 4, d4 = (idx & 15) * 4;
        int kg = kstart + row;
        bool in = (kg >= 0) && (kg < S_);
        float4 kv = in ? *(const float4*)&kb[(size_t)kg * 64 + d4]
                       : make_float4(0.f,0.f,0.f,0.f);
        float4 vv = in ? *(const float4*)&vb[(size_t)kg * 64 + d4]
                       : make_float4(0.f,0.f,0.f,0.f);
        *(float4*)&K_s[row * KSTR + d4] = kv;
        *(float4*)&V_s[row * 64 + d4]   = vv;
    }
    for (int idx = tid; idx < QT * 16; idx += AT_THREADS) {
        int r = idx >> 4, d4 = (idx & 15) * 4;
        *(float4*)&q_s[r * 64 + d4] = *(const float4*)&qb[(size_t)(q0 + r) * 64 + d4];
    }
    __syncthreads();

    const int w = tid >> 5;
    const int lane = tid & 31;
    const int s = q0 + w;
    const float* qr = q_s + w * 64;

    int   jr[5];
    bool  valid[5];
    u64   sc2[5] = {0, 0, 0, 0, 0};
    #pragma unroll
    for (int r = 0; r < 5; ++r) {
        int t = lane + 32 * r;
        int j = w + t;
        int kg = kstart + j;
        valid[r] = (t <= 128) && (kg >= 0) && (kg < S_);
        jr[r] = (j < KT_ROWS) ? j : 0;
    }
    #pragma unroll
    for (int d = 0; d < 64; d += 4) {
        ulonglong2 qp = *(const ulonglong2*)&qr[d];
        #pragma unroll
        for (int r = 0; r < 5; ++r) {
            ulonglong2 kp = *(const ulonglong2*)&K_s[jr[r] * KSTR + d];
            FMA2(sc2[r], qp.x, kp.x);
            FMA2(sc2[r], qp.y, kp.y);
        }
    }
    float sc[5];
    #pragma unroll
    for (int r = 0; r < 5; ++r) {
        float lo, hi;
        UNPACK2(lo, hi, sc2[r]);
        sc[r] = valid[r] ? (lo + hi) : -3.0e38f;
    }

    float mx = sc[0];
    #pragma unroll
    for (int r = 1; r < 5; ++r) mx = fmaxf(mx, sc[r]);
    #pragma unroll
    for (int off = 16; off > 0; off >>= 1)
        mx = fmaxf(mx, __shfl_xor_sync(0xffffffffu, mx, off));
    float sum = 0.f;
    #pragma unroll
    for (int r = 0; r < 5; ++r) { sc[r] = __expf(sc[r] - mx); sum += sc[r]; }
    #pragma unroll
    for (int off = 16; off > 0; off >>= 1)
        sum += __shfl_xor_sync(0xffffffffu, sum, off);
    float inv = 1.0f / sum;
    #pragma unroll
    for (int r = 0; r < 5; ++r) {
        int t = lane + 32 * r;
        if (t <= 128) p_s[w * 132 + t] = sc[r] * inv;
    }
    __syncwarp();

    const int d0 = lane * 2;
    u64 acc2 = 0;
    #pragma unroll 8
    for (int t = 0; t < 128; t += 4) {
        float4 p = *(const float4*)&p_s[w * 132 + t];
        u64 v0 = *(const u64*)&V_s[(w + t + 0) * 64 + d0];
        u64 v1 = *(const u64*)&V_s[(w + t + 1) * 64 + d0];
        u64 v2 = *(const u64*)&V_s[(w + t + 2) * 64 + d0];
        u64 v3 = *(const u64*)&V_s[(w + t + 3) * 64 + d0];
        u64 p0, p1, p2, p3;
        PACK2(p0, p.x); PACK2(p1, p.y); PACK2(p2, p.z); PACK2(p3, p.w);
        FMA2(acc2, p0, v0);
        FMA2(acc2, p1, v1);
        FMA2(acc2, p2, v2);
        FMA2(acc2, p3, v3);
    }
    {
        float p = p_s[w * 132 + 128];
        u64 v = *(const u64*)&V_s[(w + 128) * 64 + d0];
        u64 pp; PACK2(pp, p);
        FMA2(acc2, pp, v);
    }
    float a0, a1;
    UNPACK2(a0, a1, acc2);
    float2 o = {a0, a1};
    *(float2*)&g_attn[((size_t)(b * S_ + s)) * 256 + h * 64 + d0] = o;
}

// ======================================================================
// Kernel 3: out_proj GEMM (tf32 MMA) + fused max-pool. M=16384,N=256,K=256.
// ======================================================================
__global__ void __launch_bounds__(256) proj_pool_gemm(const float* __restrict__ W,
                                                      const float* __restrict__ bias) {
    __shared__ unsigned As[128 * ASTR];
    __shared__ unsigned Ws[128 * ASTR];

    const int tid = threadIdx.x;
    const int wid = tid >> 5, lane = tid & 31;
    const int wm = wid & 3, wn = wid >> 2;
    const int qr = lane >> 2, qc = lane & 3;
    const int m0 = blockIdx.x * 128, n0 = blockIdx.y * 128;

    float4 c[2][8] = {};

    for (int kt = 0; kt < 256; kt += 32) {
        __syncthreads();
        #pragma unroll
        for (int it = 0; it < 4; ++it) {
            int idx = tid + it * 256;
            int row = idx >> 3;
            int c4  = (idx & 7) * 4;
            float4 av = *(const float4*)&g_attn[(size_t)(m0 + row) * 256 + kt + c4];
            unsigned u0,u1,u2,u3;
            TF32(u0, av.x); TF32(u1, av.y); TF32(u2, av.z); TF32(u3, av.w);
            *(uint4*)&As[row * ASTR + c4] = make_uint4(u0,u1,u2,u3);
            float4 wv = *(const float4*)&W[(size_t)(n0 + row) * 256 + kt + c4];
            TF32(u0, wv.x); TF32(u1, wv.y); TF32(u2, wv.z); TF32(u3, wv.w);
            *(uint4*)&Ws[row * ASTR + c4] = make_uint4(u0,u1,u2,u3);
        }
        __syncthreads();
        #pragma unroll
        for (int ks = 0; ks < 4; ++ks) {
            const int k0 = ks * 8;
            unsigned a[2][4], b[8][2];
            #pragma unroll
            for (int mt = 0; mt < 2; ++mt) {
                int rb = wm * 32 + mt * 16 + qr;
                a[mt][0] = As[(rb    ) * ASTR + k0 + qc];
                a[mt][1] = As[(rb + 8) * ASTR + k0 + qc];
                a[mt][2] = As[(rb    ) * ASTR + k0 + qc + 4];
                a[mt][3] = As[(rb + 8) * ASTR + k0 + qc + 4];
            }
            #pragma unroll
            for (int nt = 0; nt < 8; ++nt) {
                int nb = wn * 64 + nt * 8 + qr;
                b[nt][0] = Ws[nb * ASTR + k0 + qc];
                b[nt][1] = Ws[nb * ASTR + k0 + qc + 4];
            }
            #pragma unroll
            for (int mt = 0; mt < 2; ++mt)
                #pragma unroll
                for (int nt = 0; nt < 8; ++nt)
                    MMA_TF32(c[mt][nt], a[mt], b[nt]);
        }
    }

    // fused max-pool: per-thread max over its 4 rows per column,
    // shfl-reduce over lane groups (xor 4,8,16) -> lanes 0..3 hold warp col-max.
    float v0[8], v1[8];
    #pragma unroll
    for (int nt = 0; nt < 8; ++nt) {
        v0[nt] = fmaxf(fmaxf(c[0][nt].x, c[0][nt].z), fmaxf(c[1][nt].x, c[1][nt].z));
        v1[nt] = fmaxf(fmaxf(c[0][nt].y, c[0][nt].w), fmaxf(c[1][nt].y, c[1][nt].w));
    }
    #pragma unroll
    for (int off = 4; off <= 16; off <<= 1) {
        #pragma unroll
        for (int nt = 0; nt < 8; ++nt) {
            v0[nt] = fmaxf(v0[nt], __shfl_xor_sync(0xffffffffu, v0[nt], off));
            v1[nt] = fmaxf(v1[nt], __shfl_xor_sync(0xffffffffu, v1[nt], off));
        }
    }
    if (lane < 4) {
        const int bb = m0 >> 11;
        #pragma unroll
        for (int nt = 0; nt < 8; ++nt) {
            int n_g = n0 + wn * 64 + nt * 8 + 2 * lane;
            atomicMax(&g_ctx_u[bb * 256 + n_g],     f2ord(v0[nt] + bias[n_g]));
            atomicMax(&g_ctx_u[bb * 256 + n_g + 1], f2ord(v1[nt] + bias[n_g + 1]));
        }
    }
}

__global__ void ctx_finalize() {
    int i = blockIdx.x * 256 + threadIdx.x;
    g_ctx[i] = ord2f(g_ctx_u[i]);
}

// ======================================================================
// MLP head: one warp per output neuron.
// ======================================================================
__global__ void __launch_bounds__(256) fc1_kernel(const float* __restrict__ w,
                                                  const float* __restrict__ bias) {
    const int gid = blockIdx.x * 8 + (threadIdx.x >> 5);
    const int lane = threadIdx.x & 31;
    const int b = gid >> 9, o = gid & 511;
    const float* wr = w + (size_t)o * 256 + lane * 8;
    const float* xr = g_ctx + b * 256 + lane * 8;
    float4 w0 = *(const float4*)wr,  w1 = *(const float4*)(wr + 4);
    float4 x0 = *(const float4*)xr,  x1 = *(const float4*)(xr + 4);
    float acc = w0.x*x0.x + w0.y*x0.y + w0.z*x0.z + w0.w*x0.w
              + w1.x*x1.x + w1.y*x1.y + w1.z*x1.z + w1.w*x1.w;
    #pragma unroll
    for (int off = 16; off > 0; off >>= 1)
        acc += __shfl_xor_sync(0xffffffffu, acc, off);
    if (lane == 0) {
        acc += bias[o];
        g_h1[gid] = acc > 0.f ? acc : 0.01f * acc;
    }
}

__global__ void __launch_bounds__(256) fc2_kernel(const float* __restrict__ w,
                                                  const float* __restrict__ bias) {
    const int gid = blockIdx.x * 8 + (threadIdx.x >> 5);
    const int lane = threadIdx.x & 31;
    const int b = gid >> 8, o = gid & 255;
    const float* wr = w + (size_t)o * 512 + lane * 16;
    const float* xr = g_h1 + b * 512 + lane * 16;
    float acc = 0.f;
    #pragma unroll
    for (int cc = 0; cc < 4; ++cc) {
        float4 wv = *(const float4*)(wr + cc * 4);
        float4 xv = *(const float4*)(xr + cc * 4);
        acc += wv.x*xv.x + wv.y*xv.y + wv.z*xv.z + wv.w*xv.w;
    }
    #pragma unroll
    for (int off = 16; off > 0; off >>= 1)
        acc += __shfl_xor_sync(0xffffffffu, acc, off);
    if (lane == 0) {
        acc += bias[o];
        g_h2[gid] = acc > 0.f ? acc : 0.01f * acc;
    }
}

__global__ void __launch_bounds__(256) fc3_kernel(const float* __restrict__ w,
                                                  const float* __restrict__ bias,
                                                  float* __restrict__ out) {
    const int gid = blockIdx.x * 8 + (threadIdx.x >> 5);
    const int lane = threadIdx.x & 31;
    if (gid >= 8 * 20) return;
    const int b = gid / 20, o = gid % 20;
    const float* wr = w + (size_t)o * 256 + lane * 8;
    const float* xr = g_h2 + b * 256 + lane * 8;
    float4 w0 = *(const float4*)wr,  w1 = *(const float4*)(wr + 4);
    float4 x0 = *(const float4*)xr,  x1 = *(const float4*)(xr + 4);
    float acc = w0.x*x0.x + w0.y*x0.y + w0.z*x0.z + w0.w*x0.w
              + w1.x*x1.x + w1.y*x1.y + w1.z*x1.z + w1.w*x1.w;
    #pragma unroll
    for (int off = 16; off > 0; off >>= 1)
        acc += __shfl_xor_sync(0xffffffffu, acc, off);
    if (lane == 0) out[b * 20 + o] = acc + bias[o];
}

// ======================================================================
extern "C" void kernel_launch(void* const* d_in, const int* in_sizes, int n_in,
                              void* d_out, int out_size) {
    const int*   text = (const int*)d_in[0];
    const float* emb  = (const float*)d_in[1];
    const float* ipw  = (const float*)d_in[2];
    const float* ipb  = (const float*)d_in[3];
    const float* opw  = (const float*)d_in[4];
    const float* opb  = (const float*)d_in[5];
    const float* fc1w = (const float*)d_in[6];
    const float* fc1b = (const float*)d_in[7];
    const float* fc2w = (const float*)d_in[8];
    const float* fc2b = (const float*)d_in[9];
    const float* fc3w = (const float*)d_in[10];
    const float* fc3b = (const float*)d_in[11];
    float* out = (float*)d_out;

    init_ctx<<<8, 256>>>();

    qkv_gemm<<<dim3(M_TOT / 128, 6), 256>>>(text, emb, ipw, ipb);

    const int attn_smem = (KT_ROWS * KSTR + KT_ROWS * 64 + QT * 64 + QT * 132) * sizeof(float);
    cudaFuncSetAttribute(attn_kernel, cudaFuncAttributeMaxDynamicSharedMemorySize, attn_smem);
    attn_kernel<<<B_ * H_ * (S_ / QT), AT_THREADS, attn_smem>>>();

    proj_pool_gemm<<<dim3(M_TOT / 128, 2), 256>>>(opw, opb);
    ctx_finalize<<<8, 256>>>();

    fc1_kernel<<<512, 256>>>(fc1w, fc1b);
    fc2_kernel<<<256, 256>>>(fc2w, fc2b);
    fc3_kernel<<<20, 256>>>(fc3w, fc3b, out);
}

// round 7
// speedup vs baseline: 8.6871x; 1.4471x over previous
#include <cuda_runtime.h>
#include <cuda_bf16.h>

#define B_   8
#define S_   2048
#define E_   256
#define H_   4
#define D_   64
#define M_TOT (B_*S_)
#define QT   16
#define WROWS 144            // QT + 2*64
#define KSTR 68              // K/Q smem stride (words)
#define VSTR 145             // V^T smem stride
#define SSTR 148             // scores stride
#define PSTR 148             // probs stride

typedef unsigned long long u64;

// tf32 helpers
#define TF32(o, x) asm("cvt.rna.tf32.f32 %0, %1;" : "=r"(o) : "f"(x))
#define MMA_TF32(c, a, b) \
    asm("mma.sync.aligned.m16n8k8.row.col.f32.tf32.tf32.f32 " \
        "{%0,%1,%2,%3}, {%4,%5,%6,%7}, {%8,%9}, {%0,%1,%2,%3};" \
        : "+f"((c).x), "+f"((c).y), "+f"((c).z), "+f"((c).w) \
        : "r"((a)[0]), "r"((a)[1]), "r"((a)[2]), "r"((a)[3]), \
          "r"((b)[0]), "r"((b)[1]))

#define ASTR 36   // GEMM smem stride

// -------- scratch --------
__device__ float g_qkv[3ull * B_ * H_ * S_ * D_];   // [sec][b][h][s][d]
__device__ float g_attn[(size_t)M_TOT * E_];        // [m][e]
__device__ unsigned int g_ctx_u[B_ * E_];
__device__ float g_ctx[B_ * E_];
__device__ float g_h1[B_ * 512];
__device__ float g_h2[B_ * 256];

__device__ __forceinline__ unsigned int f2ord(float f) {
    unsigned int u = __float_as_uint(f);
    return (u & 0x80000000u) ? ~u : (u | 0x80000000u);
}
__device__ __forceinline__ float ord2f(unsigned int u) {
    return (u & 0x80000000u) ? __uint_as_float(u & 0x7FFFFFFFu)
                             : __uint_as_float(~u);
}

__global__ void init_ctx() {
    g_ctx_u[blockIdx.x * 256 + threadIdx.x] = 0u;
}

// ======================================================================
// Kernel 1: fused embed-gather + QKV GEMM via tf32 MMA (unchanged R6).
// ======================================================================
__global__ void __launch_bounds__(256) qkv_gemm(const int* __restrict__ text,
                                                const float* __restrict__ emb,
                                                const float* __restrict__ W,
                                                const float* __restrict__ bias) {
    __shared__ unsigned As[128 * ASTR];
    __shared__ unsigned Ws[128 * ASTR];
    __shared__ int tok_s[128];

    const int tid = threadIdx.x;
    const int wid = tid >> 5, lane = tid & 31;
    const int wm = wid & 3, wn = wid >> 2;
    const int qr = lane >> 2, qc = lane & 3;
    const int m0 = blockIdx.x * 128, n0 = blockIdx.y * 128;

    if (tid < 128) tok_s[tid] = text[m0 + tid];

    float4 c[2][8] = {};

    for (int kt = 0; kt < 256; kt += 32) {
        __syncthreads();
        #pragma unroll
        for (int it = 0; it < 4; ++it) {
            int idx = tid + it * 256;
            int row = idx >> 3;
            int c4  = (idx & 7) * 4;
            float4 av = *(const float4*)&emb[(size_t)tok_s[row] * 256 + kt + c4];
            unsigned u0,u1,u2,u3;
            TF32(u0, av.x); TF32(u1, av.y); TF32(u2, av.z); TF32(u3, av.w);
            *(uint4*)&As[row * ASTR + c4] = make_uint4(u0,u1,u2,u3);
            float4 wv = *(const float4*)&W[(size_t)(n0 + row) * 256 + kt + c4];
            TF32(u0, wv.x); TF32(u1, wv.y); TF32(u2, wv.z); TF32(u3, wv.w);
            *(uint4*)&Ws[row * ASTR + c4] = make_uint4(u0,u1,u2,u3);
        }
        __syncthreads();
        #pragma unroll
        for (int ks = 0; ks < 4; ++ks) {
            const int k0 = ks * 8;
            unsigned a[2][4], b[8][2];
            #pragma unroll
            for (int mt = 0; mt < 2; ++mt) {
                int rb = wm * 32 + mt * 16 + qr;
                a[mt][0] = As[(rb    ) * ASTR + k0 + qc];
                a[mt][1] = As[(rb + 8) * ASTR + k0 + qc];
                a[mt][2] = As[(rb    ) * ASTR + k0 + qc + 4];
                a[mt][3] = As[(rb + 8) * ASTR + k0 + qc + 4];
            }
            #pragma unroll
            for (int nt = 0; nt < 8; ++nt) {
                int nb = wn * 64 + nt * 8 + qr;
                b[nt][0] = Ws[nb * ASTR + k0 + qc];
                b[nt][1] = Ws[nb * ASTR + k0 + qc + 4];
            }
            #pragma unroll
            for (int mt = 0; mt < 2; ++mt)
                #pragma unroll
                for (int nt = 0; nt < 8; ++nt)
                    MMA_TF32(c[mt][nt], a[mt], b[nt]);
        }
    }

    #pragma unroll
    for (int nt = 0; nt < 8; ++nt) {
        const int n_g = n0 + wn * 64 + nt * 8 + 2 * qc;
        const int sec = n_g >> 8;
        const int h   = (n_g >> 6) & 3;
        const int d   = n_g & 63;
        const float scale = (sec == 0) ? 0.125f : 1.0f;
        const float b0v = bias[n_g], b1v = bias[n_g + 1];
        #pragma unroll
        for (int mt = 0; mt < 2; ++mt) {
            float4 cc = c[mt][nt];
            int r = wm * 32 + mt * 16 + qr;
            #pragma unroll
            for (int half = 0; half < 2; ++half) {
                int m = m0 + r + half * 8;
                int bb = m >> 11, s = m & 2047;
                float2 o;
                o.x = ((half ? cc.z : cc.x) + b0v) * scale;
                o.y = ((half ? cc.w : cc.y) + b1v) * scale;
                *(float2*)&g_qkv[((((size_t)sec * B_ + bb) * H_ + h) * S_ + s) * 64 + d] = o;
            }
        }
    }
}

// ======================================================================
// Kernel 2: banded attention via tf32 MMA.
// Block = (b,h,16 queries), 8 warps. Dense 16x144 scores, masked softmax,
// P(16x144, tf32) x V^T(64x144) -> D(16x64).
// ======================================================================
__global__ void __launch_bounds__(256) attn_kernel() {
    extern __shared__ float smem[];
    float* K_s = smem;                    // [144][KSTR] tf32 bits
    float* Q_s = K_s + WROWS * KSTR;      // [16][KSTR]  tf32 bits
    float* V_s = Q_s + QT * KSTR;         // [64][VSTR]  tf32 bits (V transposed)
    float* S_s = V_s + 64 * VSTR;         // [16][SSTR]  fp32 scores
    float* P_s = S_s + QT * SSTR;         // [16][PSTR]  tf32 probs
    unsigned* Ku = (unsigned*)K_s;
    unsigned* Qu = (unsigned*)Q_s;
    unsigned* Vu = (unsigned*)V_s;
    unsigned* Pu = (unsigned*)P_s;

    const int nq = S_ / QT;
    const int qt = blockIdx.x % nq;
    const int h  = (blockIdx.x / nq) % H_;
    const int b  = blockIdx.x / (nq * H_);

    const int q0 = qt * QT;
    const int kstart = q0 - 64;

    const float* qb = g_qkv + ((size_t)(b * H_ + h)) * S_ * 64;
    const float* kb = g_qkv + ((size_t)(B_ * H_) + b * H_ + h) * S_ * 64;
    const float* vb = g_qkv + ((size_t)(2 * B_ * H_) + b * H_ + h) * S_ * 64;

    const int tid = threadIdx.x;
    const int wid = tid >> 5, lane = tid & 31;
    const int qr = lane >> 2, qc = lane & 3;

    // ---- stage K (tf32) and V^T (tf32) ----
    for (int idx = tid; idx < WROWS * 16; idx += 256) {
        int row = idx >> 4, d4 = (idx & 15) * 4;
        int kg = kstart + row;
        bool in = (kg >= 0) && (kg < S_);
        float4 kv = in ? *(const float4*)&kb[(size_t)kg * 64 + d4]
                       : make_float4(0.f,0.f,0.f,0.f);
        unsigned u0,u1,u2,u3;
        TF32(u0, kv.x); TF32(u1, kv.y); TF32(u2, kv.z); TF32(u3, kv.w);
        *(uint4*)&Ku[row * KSTR + d4] = make_uint4(u0,u1,u2,u3);
        float4 vv = in ? *(const float4*)&vb[(size_t)kg * 64 + d4]
                       : make_float4(0.f,0.f,0.f,0.f);
        TF32(u0, vv.x); TF32(u1, vv.y); TF32(u2, vv.z); TF32(u3, vv.w);
        Vu[(d4+0) * VSTR + row] = u0;
        Vu[(d4+1) * VSTR + row] = u1;
        Vu[(d4+2) * VSTR + row] = u2;
        Vu[(d4+3) * VSTR + row] = u3;
    }
    // ---- stage Q (tf32) ----
    if (tid < QT * 16) {
        int r = tid >> 4, d4 = (tid & 15) * 4;
        float4 qv = *(const float4*)&qb[(size_t)(q0 + r) * 64 + d4];
        unsigned u0,u1,u2,u3;
        TF32(u0, qv.x); TF32(u1, qv.y); TF32(u2, qv.z); TF32(u3, qv.w);
        *(uint4*)&Qu[r * KSTR + d4] = make_uint4(u0,u1,u2,u3);
    }
    __syncthreads();

    // ---- scores: S[16,144] = Q x K^T.  18 n-tiles over 8 warps ----
    for (int tt = wid; tt < 18; tt += 8) {
        float4 c = {0.f, 0.f, 0.f, 0.f};
        #pragma unroll
        for (int ks = 0; ks < 8; ++ks) {
            const int k0 = ks * 8;
            unsigned a[4], bf[2];
            a[0] = Qu[qr * KSTR + k0 + qc];
            a[1] = Qu[(qr + 8) * KSTR + k0 + qc];
            a[2] = Qu[qr * KSTR + k0 + qc + 4];
            a[3] = Qu[(qr + 8) * KSTR + k0 + qc + 4];
            bf[0] = Ku[(tt * 8 + qr) * KSTR + k0 + qc];
            bf[1] = Ku[(tt * 8 + qr) * KSTR + k0 + qc + 4];
            MMA_TF32(c, a, bf);
        }
        *(float2*)&S_s[qr * SSTR + tt * 8 + 2 * qc]       = make_float2(c.x, c.y);
        *(float2*)&S_s[(qr + 8) * SSTR + tt * 8 + 2 * qc] = make_float2(c.z, c.w);
    }
    __syncthreads();

    // ---- softmax: warp handles rows 2*wid, 2*wid+1 ----
    #pragma unroll
    for (int rr = 0; rr < 2; ++rr) {
        const int row = wid * 2 + rr;
        float sc[5];
        #pragma unroll
        for (int r = 0; r < 5; ++r) {
            int t = lane + 32 * r;
            int j = row + t;
            int kg = kstart + j;
            bool valid = (t <= 128) && (kg >= 0) && (kg < S_);
            sc[r] = valid ? S_s[row * SSTR + j] : -3.0e38f;
        }
        float mx = sc[0];
        #pragma unroll
        for (int r = 1; r < 5; ++r) mx = fmaxf(mx, sc[r]);
        #pragma unroll
        for (int off = 16; off > 0; off >>= 1)
            mx = fmaxf(mx, __shfl_xor_sync(0xffffffffu, mx, off));
        float sum = 0.f;
        #pragma unroll
        for (int r = 0; r < 5; ++r) { sc[r] = __expf(sc[r] - mx); sum += sc[r]; }
        #pragma unroll
        for (int off = 16; off > 0; off >>= 1)
            sum += __shfl_xor_sync(0xffffffffu, sum, off);
        float inv = 1.0f / sum;

        // zero the full row, then write the band (tf32)
        #pragma unroll
        for (int t = lane; t < WROWS; t += 32) Pu[row * PSTR + t] = 0u;
        __syncwarp();
        #pragma unroll
        for (int r = 0; r < 5; ++r) {
            int t = lane + 32 * r;
            if (t <= 128) {
                float p = sc[r] * inv;
                unsigned u; TF32(u, p);
                Pu[row * PSTR + row + t] = u;
            }
        }
        __syncwarp();
    }
    __syncthreads();

    // ---- AV: D[16,64] = P x V. warp wid owns dims [wid*8, wid*8+8) ----
    float4 d = {0.f, 0.f, 0.f, 0.f};
    #pragma unroll
    for (int ks = 0; ks < 18; ++ks) {
        const int k0 = ks * 8;
        unsigned a[4], bf[2];
        a[0] = Pu[qr * PSTR + k0 + qc];
        a[1] = Pu[(qr + 8) * PSTR + k0 + qc];
        a[2] = Pu[qr * PSTR + k0 + qc + 4];
        a[3] = Pu[(qr + 8) * PSTR + k0 + qc + 4];
        bf[0] = Vu[(wid * 8 + qr) * VSTR + k0 + qc];
        bf[1] = Vu[(wid * 8 + qr) * VSTR + k0 + qc + 4];
        MMA_TF32(d, a, bf);
    }
    const int dim = h * 64 + wid * 8 + 2 * qc;
    {
        int s = q0 + qr;
        *(float2*)&g_attn[((size_t)(b * S_ + s)) * 256 + dim] = make_float2(d.x, d.y);
        s = q0 + qr + 8;
        *(float2*)&g_attn[((size_t)(b * S_ + s)) * 256 + dim] = make_float2(d.z, d.w);
    }
}

// ======================================================================
// Kernel 3: out_proj GEMM (tf32 MMA) + fused max-pool (unchanged R6).
// ======================================================================
__global__ void __launch_bounds__(256) proj_pool_gemm(const float* __restrict__ W,
                                                      const float* __restrict__ bias) {
    __shared__ unsigned As[128 * ASTR];
    __shared__ unsigned Ws[128 * ASTR];

    const int tid = threadIdx.x;
    const int wid = tid >> 5, lane = tid & 31;
    const int wm = wid & 3, wn = wid >> 2;
    const int qr = lane >> 2, qc = lane & 3;
    const int m0 = blockIdx.x * 128, n0 = blockIdx.y * 128;

    float4 c[2][8] = {};

    for (int kt = 0; kt < 256; kt += 32) {
        __syncthreads();
        #pragma unroll
        for (int it = 0; it < 4; ++it) {
            int idx = tid + it * 256;
            int row = idx >> 3;
            int c4  = (idx & 7) * 4;
            float4 av = *(const float4*)&g_attn[(size_t)(m0 + row) * 256 + kt + c4];
            unsigned u0,u1,u2,u3;
            TF32(u0, av.x); TF32(u1, av.y); TF32(u2, av.z); TF32(u3, av.w);
            *(uint4*)&As[row * ASTR + c4] = make_uint4(u0,u1,u2,u3);
            float4 wv = *(const float4*)&W[(size_t)(n0 + row) * 256 + kt + c4];
            TF32(u0, wv.x); TF32(u1, wv.y); TF32(u2, wv.z); TF32(u3, wv.w);
            *(uint4*)&Ws[row * ASTR + c4] = make_uint4(u0,u1,u2,u3);
        }
        __syncthreads();
        #pragma unroll
        for (int ks = 0; ks < 4; ++ks) {
            const int k0 = ks * 8;
            unsigned a[2][4], b[8][2];
            #pragma unroll
            for (int mt = 0; mt < 2; ++mt) {
                int rb = wm * 32 + mt * 16 + qr;
                a[mt][0] = As[(rb    ) * ASTR + k0 + qc];
                a[mt][1] = As[(rb + 8) * ASTR + k0 + qc];
                a[mt][2] = As[(rb    ) * ASTR + k0 + qc + 4];
                a[mt][3] = As[(rb + 8) * ASTR + k0 + qc + 4];
            }
            #pragma unroll
            for (int nt = 0; nt < 8; ++nt) {
                int nb = wn * 64 + nt * 8 + qr;
                b[nt][0] = Ws[nb * ASTR + k0 + qc];
                b[nt][1] = Ws[nb * ASTR + k0 + qc + 4];
            }
            #pragma unroll
            for (int mt = 0; mt < 2; ++mt)
                #pragma unroll
                for (int nt = 0; nt < 8; ++nt)
                    MMA_TF32(c[mt][nt], a[mt], b[nt]);
        }
    }

    float v0[8], v1[8];
    #pragma unroll
    for (int nt = 0; nt < 8; ++nt) {
        v0[nt] = fmaxf(fmaxf(c[0][nt].x, c[0][nt].z), fmaxf(c[1][nt].x, c[1][nt].z));
        v1[nt] = fmaxf(fmaxf(c[0][nt].y, c[0][nt].w), fmaxf(c[1][nt].y, c[1][nt].w));
    }
    #pragma unroll
    for (int off = 4; off <= 16; off <<= 1) {
        #pragma unroll
        for (int nt = 0; nt < 8; ++nt) {
            v0[nt] = fmaxf(v0[nt], __shfl_xor_sync(0xffffffffu, v0[nt], off));
            v1[nt] = fmaxf(v1[nt], __shfl_xor_sync(0xffffffffu, v1[nt], off));
        }
    }
    if (lane < 4) {
        const int bb = m0 >> 11;
        #pragma unroll
        for (int nt = 0; nt < 8; ++nt) {
            int n_g = n0 + wn * 64 + nt * 8 + 2 * lane;
            atomicMax(&g_ctx_u[bb * 256 + n_g],     f2ord(v0[nt] + bias[n_g]));
            atomicMax(&g_ctx_u[bb * 256 + n_g + 1], f2ord(v1[nt] + bias[n_g + 1]));
        }
    }
}

__global__ void ctx_finalize() {
    int i = blockIdx.x * 256 + threadIdx.x;
    g_ctx[i] = ord2f(g_ctx_u[i]);
}

// ======================================================================
// MLP head: one warp per output neuron.
// ======================================================================
__global__ void __launch_bounds__(256) fc1_kernel(const float* __restrict__ w,
                                                  const float* __restrict__ bias) {
    const int gid = blockIdx.x * 8 + (threadIdx.x >> 5);
    const int lane = threadIdx.x & 31;
    const int b = gid >> 9, o = gid & 511;
    const float* wr = w + (size_t)o * 256 + lane * 8;
    const float* xr = g_ctx + b * 256 + lane * 8;
    float4 w0 = *(const float4*)wr,  w1 = *(const float4*)(wr + 4);
    float4 x0 = *(const float4*)xr,  x1 = *(const float4*)(xr + 4);
    float acc = w0.x*x0.x + w0.y*x0.y + w0.z*x0.z + w0.w*x0.w
              + w1.x*x1.x + w1.y*x1.y + w1.z*x1.z + w1.w*x1.w;
    #pragma unroll
    for (int off = 16; off > 0; off >>= 1)
        acc += __shfl_xor_sync(0xffffffffu, acc, off);
    if (lane == 0) {
        acc += bias[o];
        g_h1[gid] = acc > 0.f ? acc : 0.01f * acc;
    }
}

__global__ void __launch_bounds__(256) fc2_kernel(const float* __restrict__ w,
                                                  const float* __restrict__ bias) {
    const int gid = blockIdx.x * 8 + (threadIdx.x >> 5);
    const int lane = threadIdx.x & 31;
    const int b = gid >> 8, o = gid & 255;
    const float* wr = w + (size_t)o * 512 + lane * 16;
    const float* xr = g_h1 + b * 512 + lane * 16;
    float acc = 0.f;
    #pragma unroll
    for (int cc = 0; cc < 4; ++cc) {
        float4 wv = *(const float4*)(wr + cc * 4);
        float4 xv = *(const float4*)(xr + cc * 4);
        acc += wv.x*xv.x + wv.y*xv.y + wv.z*xv.z + wv.w*xv.w;
    }
    #pragma unroll
    for (int off = 16; off > 0; off >>= 1)
        acc += __shfl_xor_sync(0xffffffffu, acc, off);
    if (lane == 0) {
        acc += bias[o];
        g_h2[gid] = acc > 0.f ? acc : 0.01f * acc;
    }
}

__global__ void __launch_bounds__(256) fc3_kernel(const float* __restrict__ w,
                                                  const float* __restrict__ bias,
                                                  float* __restrict__ out) {
    const int gid = blockIdx.x * 8 + (threadIdx.x >> 5);
    const int lane = threadIdx.x & 31;
    if (gid >= 8 * 20) return;
    const int b = gid / 20, o = gid % 20;
    const float* wr = w + (size_t)o * 256 + lane * 8;
    const float* xr = g_h2 + b * 256 + lane * 8;
    float4 w0 = *(const float4*)wr,  w1 = *(const float4*)(wr + 4);
    float4 x0 = *(const float4*)xr,  x1 = *(const float4*)(xr + 4);
    float acc = w0.x*x0.x + w0.y*x0.y + w0.z*x0.z + w0.w*x0.w
              + w1.x*x1.x + w1.y*x1.y + w1.z*x1.z + w1.w*x1.w;
    #pragma unroll
    for (int off = 16; off > 0; off >>= 1)
        acc += __shfl_xor_sync(0xffffffffu, acc, off);
    if (lane == 0) out[b * 20 + o] = acc + bias[o];
}

// ======================================================================
extern "C" void kernel_launch(void* const* d_in, const int* in_sizes, int n_in,
                              void* d_out, int out_size) {
    const int*   text = (const int*)d_in[0];
    const float* emb  = (const float*)d_in[1];
    const float* ipw  = (const float*)d_in[2];
    const float* ipb  = (const float*)d_in[3];
    const float* opw  = (const float*)d_in[4];
    const float* opb  = (const float*)d_in[5];
    const float* fc1w = (const float*)d_in[6];
    const float* fc1b = (const float*)d_in[7];
    const float* fc2w = (const float*)d_in[8];
    const float* fc2b = (const float*)d_in[9];
    const float* fc3w = (const float*)d_in[10];
    const float* fc3b = (const float*)d_in[11];
    float* out = (float*)d_out;

    init_ctx<<<8, 256>>>();

    qkv_gemm<<<dim3(M_TOT / 128, 6), 256>>>(text, emb, ipw, ipb);

    const int attn_smem = (WROWS * KSTR + QT * KSTR + 64 * VSTR
                           + QT * SSTR + QT * PSTR) * sizeof(float);
    cudaFuncSetAttribute(attn_kernel, cudaFuncAttributeMaxDynamicSharedMemorySize, attn_smem);
    attn_kernel<<<B_ * H_ * (S_ / QT), 256, attn_smem>>>();

    proj_pool_gemm<<<dim3(M_TOT / 128, 2), 256>>>(opw, opb);
    ctx_finalize<<<8, 256>>>();

    fc1_kernel<<<512, 256>>>(fc1w, fc1b);
    fc2_kernel<<<256, 256>>>(fc2w, fc2b);
    fc3_kernel<<<20, 256>>>(fc3w, fc3b, out);
}